// round 4
// baseline (speedup 1.0000x reference)
#include <cuda_runtime.h>
#include <math.h>

#define TOK   4096          // B*S
#define SEQ   2048
#define DM    1024
#define DFF   4096
#define NH    16
#define DH    64
#define EPSLN 1e-5f

// ---------------- scratch (device globals; no allocation allowed) ----------
__device__ __align__(256) float g_q[TOK * DM];
__device__ __align__(256) float g_k[TOK * DM];
__device__ __align__(256) float g_v[TOK * DM];
__device__ __align__(256) float g_attnc[TOK * DM];
__device__ __align__(256) float g_tmp[TOK * DM];
__device__ __align__(256) float g_h[TOK * DM];
__device__ __align__(256) float g_ff[TOK * DFF];

// ---------------------------------------------------------------------------
// GEMM: C[M,N] = A[M,K] @ W[N,K]^T + bias  (optional ReLU)
// 64x64 tile, BK=16, 256 threads, 4x4 accum per thread. M,N,K all % 64/16 == 0.
// ---------------------------------------------------------------------------
__global__ __launch_bounds__(256) void gemm_bias(
    const float* __restrict__ A, const float* __restrict__ W,
    const float* __restrict__ bias, float* __restrict__ C,
    int M, int N, int K, int relu)
{
    __shared__ float As[16][64];   // [k][m]
    __shared__ float Ws[16][64];   // [k][n]

    const int tx = threadIdx.x % 16;      // n sub-tile
    const int ty = threadIdx.x / 16;      // m sub-tile
    const int lrow = threadIdx.x / 4;     // 0..63  (load row)
    const int lc4  = threadIdx.x % 4;     // 0..3   (load float4 col)

    const int m0 = blockIdx.y * 64;
    const int n0 = blockIdx.x * 64;

    float acc[4][4] = {};

    for (int k0 = 0; k0 < K; k0 += 16) {
        float4 av = *(const float4*)&A[(size_t)(m0 + lrow) * K + k0 + lc4 * 4];
        float4 wv = *(const float4*)&W[(size_t)(n0 + lrow) * K + k0 + lc4 * 4];
        As[lc4 * 4 + 0][lrow] = av.x;
        As[lc4 * 4 + 1][lrow] = av.y;
        As[lc4 * 4 + 2][lrow] = av.z;
        As[lc4 * 4 + 3][lrow] = av.w;
        Ws[lc4 * 4 + 0][lrow] = wv.x;
        Ws[lc4 * 4 + 1][lrow] = wv.y;
        Ws[lc4 * 4 + 2][lrow] = wv.z;
        Ws[lc4 * 4 + 3][lrow] = wv.w;
        __syncthreads();

        #pragma unroll
        for (int k = 0; k < 16; k++) {
            float4 a = *(const float4*)&As[k][ty * 4];
            float4 b = *(const float4*)&Ws[k][tx * 4];
            acc[0][0] += a.x * b.x; acc[0][1] += a.x * b.y;
            acc[0][2] += a.x * b.z; acc[0][3] += a.x * b.w;
            acc[1][0] += a.y * b.x; acc[1][1] += a.y * b.y;
            acc[1][2] += a.y * b.z; acc[1][3] += a.y * b.w;
            acc[2][0] += a.z * b.x; acc[2][1] += a.z * b.y;
            acc[2][2] += a.z * b.z; acc[2][3] += a.z * b.w;
            acc[3][0] += a.w * b.x; acc[3][1] += a.w * b.y;
            acc[3][2] += a.w * b.z; acc[3][3] += a.w * b.w;
        }
        __syncthreads();
    }

    float4 bv = *(const float4*)&bias[n0 + tx * 4];
    #pragma unroll
    for (int i = 0; i < 4; i++) {
        float4 o;
        o.x = acc[i][0] + bv.x;
        o.y = acc[i][1] + bv.y;
        o.z = acc[i][2] + bv.z;
        o.w = acc[i][3] + bv.w;
        if (relu) {
            o.x = fmaxf(o.x, 0.f); o.y = fmaxf(o.y, 0.f);
            o.z = fmaxf(o.z, 0.f); o.w = fmaxf(o.w, 0.f);
        }
        *(float4*)&C[(size_t)(m0 + ty * 4 + i) * N + n0 + tx * 4] = o;
    }
}

// ---------------------------------------------------------------------------
// Flash attention, fp32, head_dim=64, query tile 64, key tile 64.
// grid = (SEQ/64, B*NH), block = 256 threads. Dynamic smem ~70KB.
// Q/K/V layout: [b*SEQ + s][h*64 + d] (output of the QKV GEMMs).
// Output written in "concat heads" layout to match Wo GEMM input.
// ---------------------------------------------------------------------------
#define SP 68   // padded stride (floats): %4==0 for float4 align, %32!=0 vs conflicts

__global__ __launch_bounds__(256) void flash_attn(
    const float* __restrict__ Q, const float* __restrict__ K,
    const float* __restrict__ V, float* __restrict__ O)
{
    extern __shared__ float sm[];
    float* Qs  = sm;              // [d][q]  64*SP
    float* Ks  = Qs + 64 * SP;    // [d][k]
    float* Vs  = Ks + 64 * SP;    // [k][d]
    float* Ps  = Vs + 64 * SP;    // [k][q]  (scores, then probabilities)
    float* m_s = Ps + 64 * SP;    // [64] running max
    float* l_s = m_s + 64;        // [64] running sum
    float* a_s = l_s + 64;        // [64] rescale factor

    const int bh = blockIdx.y;
    const int b = bh / NH, h = bh % NH;
    const int q0 = blockIdx.x * 64;
    const int tx = threadIdx.x % 16;
    const int ty = threadIdx.x / 16;
    const int lrow = threadIdx.x / 4;
    const int lc4  = threadIdx.x % 4;
    const float scale = 0.125f;   // 1/sqrt(64)

    // Load Q tile (transposed [d][q], pre-scaled)
    {
        const float* qp = Q + ((size_t)(b * SEQ + q0 + lrow)) * DM + h * DH;
        #pragma unroll
        for (int c = 0; c < 4; c++) {
            int d0 = (lc4 + 4 * c) * 4;
            float4 v4 = *(const float4*)&qp[d0];
            Qs[(d0 + 0) * SP + lrow] = v4.x * scale;
            Qs[(d0 + 1) * SP + lrow] = v4.y * scale;
            Qs[(d0 + 2) * SP + lrow] = v4.z * scale;
            Qs[(d0 + 3) * SP + lrow] = v4.w * scale;
        }
    }
    if (threadIdx.x < 64) { m_s[threadIdx.x] = -1e30f; l_s[threadIdx.x] = 0.f; }

    float acc[4][4] = {};

    for (int kt = 0; kt < SEQ; kt += 64) {
        __syncthreads();   // previous iter done with Ks/Vs; Q/m/l init visible
        {
            const float* kp = K + ((size_t)(b * SEQ + kt + lrow)) * DM + h * DH;
            const float* vp = V + ((size_t)(b * SEQ + kt + lrow)) * DM + h * DH;
            #pragma unroll
            for (int c = 0; c < 4; c++) {
                int d0 = (lc4 + 4 * c) * 4;
                float4 kv = *(const float4*)&kp[d0];
                Ks[(d0 + 0) * SP + lrow] = kv.x;
                Ks[(d0 + 1) * SP + lrow] = kv.y;
                Ks[(d0 + 2) * SP + lrow] = kv.z;
                Ks[(d0 + 3) * SP + lrow] = kv.w;
                float4 vv = *(const float4*)&vp[d0];
                *(float4*)&Vs[lrow * SP + d0] = vv;
            }
        }
        __syncthreads();

        // GEMM1: S = (Q*scale) @ K^T  -> Ps[k][q]
        float s[4][4] = {};
        #pragma unroll 8
        for (int d = 0; d < 64; d++) {
            float4 a = *(const float4*)&Qs[d * SP + ty * 4];
            float4 bb = *(const float4*)&Ks[d * SP + tx * 4];
            s[0][0] += a.x * bb.x; s[0][1] += a.x * bb.y;
            s[0][2] += a.x * bb.z; s[0][3] += a.x * bb.w;
            s[1][0] += a.y * bb.x; s[1][1] += a.y * bb.y;
            s[1][2] += a.y * bb.z; s[1][3] += a.y * bb.w;
            s[2][0] += a.z * bb.x; s[2][1] += a.z * bb.y;
            s[2][2] += a.z * bb.z; s[2][3] += a.z * bb.w;
            s[3][0] += a.w * bb.x; s[3][1] += a.w * bb.y;
            s[3][2] += a.w * bb.z; s[3][3] += a.w * bb.w;
        }
        #pragma unroll
        for (int j = 0; j < 4; j++)
            #pragma unroll
            for (int i = 0; i < 4; i++)
                Ps[(tx * 4 + j) * SP + ty * 4 + i] = s[i][j];
        __syncthreads();

        // Online softmax: one thread per query row
        if (threadIdx.x < 64) {
            const int q = threadIdx.x;
            float tmax = -1e30f;
            #pragma unroll 8
            for (int k2 = 0; k2 < 64; k2++)
                tmax = fmaxf(tmax, Ps[k2 * SP + q]);
            const float mold = m_s[q];
            const float mnew = fmaxf(mold, tmax);
            const float alpha = __expf(mold - mnew);
            float sum = 0.f;
            #pragma unroll 8
            for (int k2 = 0; k2 < 64; k2++) {
                float p = __expf(Ps[k2 * SP + q] - mnew);
                Ps[k2 * SP + q] = p;
                sum += p;
            }
            l_s[q] = l_s[q] * alpha + sum;
            m_s[q] = mnew;
            a_s[q] = alpha;
        }
        __syncthreads();

        // Rescale accumulator, then GEMM2: O += P @ V
        #pragma unroll
        for (int i = 0; i < 4; i++) {
            float al = a_s[ty * 4 + i];
            acc[i][0] *= al; acc[i][1] *= al; acc[i][2] *= al; acc[i][3] *= al;
        }
        #pragma unroll 8
        for (int k2 = 0; k2 < 64; k2++) {
            float4 p  = *(const float4*)&Ps[k2 * SP + ty * 4];
            float4 vv = *(const float4*)&Vs[k2 * SP + tx * 4];
            acc[0][0] += p.x * vv.x; acc[0][1] += p.x * vv.y;
            acc[0][2] += p.x * vv.z; acc[0][3] += p.x * vv.w;
            acc[1][0] += p.y * vv.x; acc[1][1] += p.y * vv.y;
            acc[1][2] += p.y * vv.z; acc[1][3] += p.y * vv.w;
            acc[2][0] += p.z * vv.x; acc[2][1] += p.z * vv.y;
            acc[2][2] += p.z * vv.z; acc[2][3] += p.z * vv.w;
            acc[3][0] += p.w * vv.x; acc[3][1] += p.w * vv.y;
            acc[3][2] += p.w * vv.z; acc[3][3] += p.w * vv.w;
        }
    }

    // Write normalized output in concat-heads layout
    #pragma unroll
    for (int i = 0; i < 4; i++) {
        const float inv_l = 1.0f / l_s[ty * 4 + i];
        float4 o;
        o.x = acc[i][0] * inv_l;
        o.y = acc[i][1] * inv_l;
        o.z = acc[i][2] * inv_l;
        o.w = acc[i][3] * inv_l;
        *(float4*)&O[((size_t)(b * SEQ + q0 + ty * 4 + i)) * DM + h * DH + tx * 4] = o;
    }
}

// ---------------------------------------------------------------------------
// Fused residual add + LayerNorm over last dim (1024). One block per row.
// ---------------------------------------------------------------------------
__global__ __launch_bounds__(256) void add_ln(
    const float* __restrict__ X, const float* __restrict__ Y,
    const float* __restrict__ gamma, const float* __restrict__ beta,
    float* __restrict__ out)
{
    __shared__ float red[256];
    const int row = blockIdx.x;
    const int tid = threadIdx.x;
    const float* xp = X + (size_t)row * DM;
    const float* yp = Y + (size_t)row * DM;

    float4 a = *(const float4*)&xp[tid * 4];
    float4 b = *(const float4*)&yp[tid * 4];
    float v0 = a.x + b.x, v1 = a.y + b.y, v2 = a.z + b.z, v3 = a.w + b.w;

    red[tid] = v0 + v1 + v2 + v3;
    __syncthreads();
    for (int o = 128; o > 0; o >>= 1) {
        if (tid < o) red[tid] += red[tid + o];
        __syncthreads();
    }
    const float mean = red[0] * (1.0f / DM);
    __syncthreads();

    v0 -= mean; v1 -= mean; v2 -= mean; v3 -= mean;
    red[tid] = v0 * v0 + v1 * v1 + v2 * v2 + v3 * v3;
    __syncthreads();
    for (int o = 128; o > 0; o >>= 1) {
        if (tid < o) red[tid] += red[tid + o];
        __syncthreads();
    }
    const float rstd = rsqrtf(red[0] * (1.0f / DM) + EPSLN);

    float4 g = *(const float4*)&gamma[tid * 4];
    float4 be = *(const float4*)&beta[tid * 4];
    float4 o4;
    o4.x = v0 * rstd * g.x + be.x;
    o4.y = v1 * rstd * g.y + be.y;
    o4.z = v2 * rstd * g.z + be.z;
    o4.w = v3 * rstd * g.w + be.w;
    *(float4*)&out[(size_t)row * DM + tid * 4] = o4;
}

// ---------------------------------------------------------------------------
#define FLASH_SMEM ((4 * 64 * SP + 3 * 64) * (int)sizeof(float))

extern "C" void kernel_launch(void* const* d_in, const int* in_sizes, int n_in,
                              void* d_out, int out_size)
{
    const float* x   = (const float*)d_in[0];
    const float* Wq  = (const float*)d_in[1];
    const float* bq  = (const float*)d_in[2];
    const float* Wk  = (const float*)d_in[3];
    const float* bk  = (const float*)d_in[4];
    const float* Wv  = (const float*)d_in[5];
    const float* bv  = (const float*)d_in[6];
    const float* Wo  = (const float*)d_in[7];
    const float* bo  = (const float*)d_in[8];
    const float* W1  = (const float*)d_in[9];
    const float* b1  = (const float*)d_in[10];
    const float* W2  = (const float*)d_in[11];
    const float* b2  = (const float*)d_in[12];
    const float* g1  = (const float*)d_in[13];
    const float* be1 = (const float*)d_in[14];
    const float* g2  = (const float*)d_in[15];
    const float* be2 = (const float*)d_in[16];
    float* out = (float*)d_out;

    float *q, *k, *v, *attnc, *tmp, *h, *ff;
    cudaGetSymbolAddress((void**)&q, g_q);
    cudaGetSymbolAddress((void**)&k, g_k);
    cudaGetSymbolAddress((void**)&v, g_v);
    cudaGetSymbolAddress((void**)&attnc, g_attnc);
    cudaGetSymbolAddress((void**)&tmp, g_tmp);
    cudaGetSymbolAddress((void**)&h, g_h);
    cudaGetSymbolAddress((void**)&ff, g_ff);

    cudaFuncSetAttribute(flash_attn,
                         cudaFuncAttributeMaxDynamicSharedMemorySize, FLASH_SMEM);

    // QKV projections
    gemm_bias<<<dim3(DM / 64, TOK / 64), 256>>>(x, Wq, bq, q, TOK, DM, DM, 0);
    gemm_bias<<<dim3(DM / 64, TOK / 64), 256>>>(x, Wk, bk, k, TOK, DM, DM, 0);
    gemm_bias<<<dim3(DM / 64, TOK / 64), 256>>>(x, Wv, bv, v, TOK, DM, DM, 0);

    // Attention
    flash_attn<<<dim3(SEQ / 64, 2 * NH), 256, FLASH_SMEM>>>(q, k, v, attnc);

    // Output projection + residual + LN1
    gemm_bias<<<dim3(DM / 64, TOK / 64), 256>>>(attnc, Wo, bo, tmp, TOK, DM, DM, 0);
    add_ln<<<TOK, 256>>>(x, tmp, g1, be1, h);

    // FFN
    gemm_bias<<<dim3(DFF / 64, TOK / 64), 256>>>(h, W1, b1, ff, TOK, DFF, DM, 1);
    gemm_bias<<<dim3(DM / 64, TOK / 64), 256>>>(ff, W2, b2, tmp, TOK, DM, DFF, 0);

    // Residual + LN2 -> output
    add_ln<<<TOK, 256>>>(h, tmp, g2, be2, out);
}

// round 5
// speedup vs baseline: 3.3009x; 3.3009x over previous
#include <cuda_runtime.h>
#include <cuda_bf16.h>
#include <math.h>
#include <stdint.h>

#define TOK   4096          // B*S
#define SEQ   2048
#define DM    1024
#define DFF   4096
#define NH    16
#define DH    64
#define EPSLN 1e-5f

// ---------------- scratch (device globals; no allocation allowed) ----------
__device__ __align__(256) float g_q[TOK * DM];
__device__ __align__(256) float g_k[TOK * DM];
__device__ __align__(256) float g_v[TOK * DM];
__device__ __align__(256) float g_attnc[TOK * DM];
__device__ __align__(256) float g_tmp[TOK * DM];
__device__ __align__(256) float g_h[TOK * DM];
__device__ __align__(256) float g_ff[TOK * DFF];

// split-bf16 operand buffers (hi / lo)
__device__ __align__(256) __nv_bfloat16 g_xh[TOK * DM],  g_xl[TOK * DM];
__device__ __align__(256) __nv_bfloat16 g_ach[TOK * DM], g_acl[TOK * DM];
__device__ __align__(256) __nv_bfloat16 g_hh[TOK * DM],  g_hl[TOK * DM];
__device__ __align__(256) __nv_bfloat16 g_ffh[TOK * DFF], g_ffl[TOK * DFF];
__device__ __align__(256) __nv_bfloat16 g_Wqh[DM * DM],  g_Wql[DM * DM];
__device__ __align__(256) __nv_bfloat16 g_Wkh[DM * DM],  g_Wkl[DM * DM];
__device__ __align__(256) __nv_bfloat16 g_Wvh[DM * DM],  g_Wvl[DM * DM];
__device__ __align__(256) __nv_bfloat16 g_Woh[DM * DM],  g_Wol[DM * DM];
__device__ __align__(256) __nv_bfloat16 g_W1h[DFF * DM], g_W1l[DFF * DM];
__device__ __align__(256) __nv_bfloat16 g_W2h[DM * DFF], g_W2l[DM * DFF];

// ---------------------------------------------------------------------------
// fp32 -> (bf16 hi, bf16 lo) split conversion. n4 = element_count / 4.
// ---------------------------------------------------------------------------
__global__ __launch_bounds__(256) void f32_split(
    const float* __restrict__ X,
    __nv_bfloat16* __restrict__ H, __nv_bfloat16* __restrict__ L, int n4)
{
    int i = blockIdx.x * blockDim.x + threadIdx.x;
    if (i >= n4) return;
    float4 v = ((const float4*)X)[i];
    __nv_bfloat16 h0 = __float2bfloat16_rn(v.x);
    __nv_bfloat16 h1 = __float2bfloat16_rn(v.y);
    __nv_bfloat16 h2 = __float2bfloat16_rn(v.z);
    __nv_bfloat16 h3 = __float2bfloat16_rn(v.w);
    __nv_bfloat16 l0 = __float2bfloat16_rn(v.x - __bfloat162float(h0));
    __nv_bfloat16 l1 = __float2bfloat16_rn(v.y - __bfloat162float(h1));
    __nv_bfloat16 l2 = __float2bfloat16_rn(v.z - __bfloat162float(h2));
    __nv_bfloat16 l3 = __float2bfloat16_rn(v.w - __bfloat162float(h3));
    __nv_bfloat162 hp0 = __nv_bfloat162(h0, h1), hp1 = __nv_bfloat162(h2, h3);
    __nv_bfloat162 lp0 = __nv_bfloat162(l0, l1), lp1 = __nv_bfloat162(l2, l3);
    ((__nv_bfloat162*)H)[i * 2 + 0] = hp0;
    ((__nv_bfloat162*)H)[i * 2 + 1] = hp1;
    ((__nv_bfloat162*)L)[i * 2 + 0] = lp0;
    ((__nv_bfloat162*)L)[i * 2 + 1] = lp1;
}

// ---------------------------------------------------------------------------
// Tensor-core GEMM (split-bf16, 3 mma passes): C[M,N] = A[M,K] @ W[N,K]^T + b
// Block tile 128x128, BK=32, 256 thr = 8 warps (4 M x 2 N), warp tile 32x64.
// ---------------------------------------------------------------------------
#define BM  128
#define BN  128
#define BKg 32
#define LDSM_STRIDE (BKg + 8)   // 40 bf16 = 80 bytes: conflict-free ldmatrix

__device__ __forceinline__ uint32_t smem_u32(const void* p) {
    return (uint32_t)__cvta_generic_to_shared(p);
}
__device__ __forceinline__ void ldsm_x4(uint32_t& r0, uint32_t& r1,
                                        uint32_t& r2, uint32_t& r3, uint32_t a) {
    asm volatile("ldmatrix.sync.aligned.m8n8.x4.shared.b16 {%0,%1,%2,%3}, [%4];"
                 : "=r"(r0), "=r"(r1), "=r"(r2), "=r"(r3) : "r"(a));
}
__device__ __forceinline__ void mma16816(float* c, const uint32_t* a,
                                         const uint32_t* b) {
    asm volatile(
        "mma.sync.aligned.m16n8k16.row.col.f32.bf16.bf16.f32 "
        "{%0,%1,%2,%3}, {%4,%5,%6,%7}, {%8,%9}, {%0,%1,%2,%3};"
        : "+f"(c[0]), "+f"(c[1]), "+f"(c[2]), "+f"(c[3])
        : "r"(a[0]), "r"(a[1]), "r"(a[2]), "r"(a[3]), "r"(b[0]), "r"(b[1]));
}

__global__ __launch_bounds__(256) void gemm_mma(
    const __nv_bfloat16* __restrict__ Ah, const __nv_bfloat16* __restrict__ Al,
    const __nv_bfloat16* __restrict__ Wh, const __nv_bfloat16* __restrict__ Wl,
    const float* __restrict__ bias, float* __restrict__ C,
    int M, int N, int K, int relu)
{
    __shared__ __nv_bfloat16 Ash[BM][LDSM_STRIDE], Asl[BM][LDSM_STRIDE];
    __shared__ __nv_bfloat16 Wsh[BN][LDSM_STRIDE], Wsl[BN][LDSM_STRIDE];

    const int tid  = threadIdx.x;
    const int lane = tid & 31;
    const int warp = tid >> 5;
    const int wm = (warp >> 1) * 32;   // warp M offset in block tile
    const int wn = (warp & 1) * 64;    // warp N offset
    const int m0 = blockIdx.y * BM;
    const int n0 = blockIdx.x * BN;

    float acc[2][8][4] = {};

    // ldmatrix source coordinates (computed once)
    const int a_row = (lane & 15);            // + wm + mt*16
    const int a_col = (lane >> 4) << 3;       // + kk*16
    const int b_row = ((lane >> 4) << 3) + (lane & 7);  // + wn + p*16
    const int b_col = ((lane >> 3) & 1) << 3;           // + kk*16

    for (int kb = 0; kb < K; kb += BKg) {
        // ---- global -> shared (bf16, 16B chunks). 512 chunks per tile array.
        #pragma unroll
        for (int i = 0; i < 2; i++) {
            int chunk = tid + i * 256;      // 0..511
            int row = chunk >> 2;           // 0..127
            int c   = chunk & 3;            // 16B chunk within 32-elem row
            const uint4* pa_h = (const uint4*)(Ah + (size_t)(m0 + row) * K + kb) + c;
            const uint4* pa_l = (const uint4*)(Al + (size_t)(m0 + row) * K + kb) + c;
            const uint4* pw_h = (const uint4*)(Wh + (size_t)(n0 + row) * K + kb) + c;
            const uint4* pw_l = (const uint4*)(Wl + (size_t)(n0 + row) * K + kb) + c;
            *(uint4*)&Ash[row][c * 8] = *pa_h;
            *(uint4*)&Asl[row][c * 8] = *pa_l;
            *(uint4*)&Wsh[row][c * 8] = *pw_h;
            *(uint4*)&Wsl[row][c * 8] = *pw_l;
        }
        __syncthreads();

        #pragma unroll
        for (int kk = 0; kk < 2; kk++) {
            // A fragments (hi & lo), 2 m-tiles
            uint32_t afh[2][4], afl[2][4];
            #pragma unroll
            for (int mt = 0; mt < 2; mt++) {
                int r = wm + mt * 16 + a_row;
                int c = kk * 16 + a_col;
                ldsm_x4(afh[mt][0], afh[mt][1], afh[mt][2], afh[mt][3],
                        smem_u32(&Ash[r][c]));
                ldsm_x4(afl[mt][0], afl[mt][1], afl[mt][2], afl[mt][3],
                        smem_u32(&Asl[r][c]));
            }
            // B fragments (hi & lo), 8 n-tiles loaded pairwise via x4
            uint32_t bfh[8][2], bfl[8][2];
            #pragma unroll
            for (int p = 0; p < 4; p++) {
                int r = wn + p * 16 + b_row;
                int c = kk * 16 + b_col;
                uint32_t r0, r1, r2, r3;
                ldsm_x4(r0, r1, r2, r3, smem_u32(&Wsh[r][c]));
                bfh[2 * p][0] = r0; bfh[2 * p][1] = r1;
                bfh[2 * p + 1][0] = r2; bfh[2 * p + 1][1] = r3;
                ldsm_x4(r0, r1, r2, r3, smem_u32(&Wsl[r][c]));
                bfl[2 * p][0] = r0; bfl[2 * p][1] = r1;
                bfl[2 * p + 1][0] = r2; bfl[2 * p + 1][1] = r3;
            }
            // 3-pass split accumulation: hi*hi + hi*lo + lo*hi
            #pragma unroll
            for (int mt = 0; mt < 2; mt++)
                #pragma unroll
                for (int nt = 0; nt < 8; nt++) {
                    mma16816(acc[mt][nt], afh[mt], bfh[nt]);
                    mma16816(acc[mt][nt], afh[mt], bfl[nt]);
                    mma16816(acc[mt][nt], afl[mt], bfh[nt]);
                }
        }
        __syncthreads();
    }

    // ---- epilogue: bias (+ReLU), fp32 out
    const int er = lane >> 2;            // row within 16-tile (0..7)
    const int ec = (lane & 3) * 2;       // col pair
    #pragma unroll
    for (int mt = 0; mt < 2; mt++) {
        #pragma unroll
        for (int nt = 0; nt < 8; nt++) {
            int row = m0 + wm + mt * 16 + er;
            int col = n0 + wn + nt * 8 + ec;
            float2 b2 = *(const float2*)&bias[col];
            float2 o0, o1;
            o0.x = acc[mt][nt][0] + b2.x;  o0.y = acc[mt][nt][1] + b2.y;
            o1.x = acc[mt][nt][2] + b2.x;  o1.y = acc[mt][nt][3] + b2.y;
            if (relu) {
                o0.x = fmaxf(o0.x, 0.f); o0.y = fmaxf(o0.y, 0.f);
                o1.x = fmaxf(o1.x, 0.f); o1.y = fmaxf(o1.y, 0.f);
            }
            *(float2*)&C[(size_t)row * N + col]       = o0;
            *(float2*)&C[(size_t)(row + 8) * N + col] = o1;
        }
    }
}

// ---------------------------------------------------------------------------
// Flash attention, fp32, head_dim=64, query tile 64, key tile 64. (unchanged)
// ---------------------------------------------------------------------------
#define SP 68

__global__ __launch_bounds__(256) void flash_attn(
    const float* __restrict__ Q, const float* __restrict__ K,
    const float* __restrict__ V, float* __restrict__ O)
{
    extern __shared__ float sm[];
    float* Qs  = sm;
    float* Ks  = Qs + 64 * SP;
    float* Vs  = Ks + 64 * SP;
    float* Ps  = Vs + 64 * SP;
    float* m_s = Ps + 64 * SP;
    float* l_s = m_s + 64;
    float* a_s = l_s + 64;

    const int bh = blockIdx.y;
    const int b = bh / NH, h = bh % NH;
    const int q0 = blockIdx.x * 64;
    const int tx = threadIdx.x % 16;
    const int ty = threadIdx.x / 16;
    const int lrow = threadIdx.x / 4;
    const int lc4  = threadIdx.x % 4;
    const float scale = 0.125f;

    {
        const float* qp = Q + ((size_t)(b * SEQ + q0 + lrow)) * DM + h * DH;
        #pragma unroll
        for (int c = 0; c < 4; c++) {
            int d0 = (lc4 + 4 * c) * 4;
            float4 v4 = *(const float4*)&qp[d0];
            Qs[(d0 + 0) * SP + lrow] = v4.x * scale;
            Qs[(d0 + 1) * SP + lrow] = v4.y * scale;
            Qs[(d0 + 2) * SP + lrow] = v4.z * scale;
            Qs[(d0 + 3) * SP + lrow] = v4.w * scale;
        }
    }
    if (threadIdx.x < 64) { m_s[threadIdx.x] = -1e30f; l_s[threadIdx.x] = 0.f; }

    float acc[4][4] = {};

    for (int kt = 0; kt < SEQ; kt += 64) {
        __syncthreads();
        {
            const float* kp = K + ((size_t)(b * SEQ + kt + lrow)) * DM + h * DH;
            const float* vp = V + ((size_t)(b * SEQ + kt + lrow)) * DM + h * DH;
            #pragma unroll
            for (int c = 0; c < 4; c++) {
                int d0 = (lc4 + 4 * c) * 4;
                float4 kv = *(const float4*)&kp[d0];
                Ks[(d0 + 0) * SP + lrow] = kv.x;
                Ks[(d0 + 1) * SP + lrow] = kv.y;
                Ks[(d0 + 2) * SP + lrow] = kv.z;
                Ks[(d0 + 3) * SP + lrow] = kv.w;
                float4 vv = *(const float4*)&vp[d0];
                *(float4*)&Vs[lrow * SP + d0] = vv;
            }
        }
        __syncthreads();

        float s[4][4] = {};
        #pragma unroll 8
        for (int d = 0; d < 64; d++) {
            float4 a = *(const float4*)&Qs[d * SP + ty * 4];
            float4 bb = *(const float4*)&Ks[d * SP + tx * 4];
            s[0][0] += a.x * bb.x; s[0][1] += a.x * bb.y;
            s[0][2] += a.x * bb.z; s[0][3] += a.x * bb.w;
            s[1][0] += a.y * bb.x; s[1][1] += a.y * bb.y;
            s[1][2] += a.y * bb.z; s[1][3] += a.y * bb.w;
            s[2][0] += a.z * bb.x; s[2][1] += a.z * bb.y;
            s[2][2] += a.z * bb.z; s[2][3] += a.z * bb.w;
            s[3][0] += a.w * bb.x; s[3][1] += a.w * bb.y;
            s[3][2] += a.w * bb.z; s[3][3] += a.w * bb.w;
        }
        #pragma unroll
        for (int j = 0; j < 4; j++)
            #pragma unroll
            for (int i = 0; i < 4; i++)
                Ps[(tx * 4 + j) * SP + ty * 4 + i] = s[i][j];
        __syncthreads();

        if (threadIdx.x < 64) {
            const int q = threadIdx.x;
            float tmax = -1e30f;
            #pragma unroll 8
            for (int k2 = 0; k2 < 64; k2++)
                tmax = fmaxf(tmax, Ps[k2 * SP + q]);
            const float mold = m_s[q];
            const float mnew = fmaxf(mold, tmax);
            const float alpha = __expf(mold - mnew);
            float sum = 0.f;
            #pragma unroll 8
            for (int k2 = 0; k2 < 64; k2++) {
                float p = __expf(Ps[k2 * SP + q] - mnew);
                Ps[k2 * SP + q] = p;
                sum += p;
            }
            l_s[q] = l_s[q] * alpha + sum;
            m_s[q] = mnew;
            a_s[q] = alpha;
        }
        __syncthreads();

        #pragma unroll
        for (int i = 0; i < 4; i++) {
            float al = a_s[ty * 4 + i];
            acc[i][0] *= al; acc[i][1] *= al; acc[i][2] *= al; acc[i][3] *= al;
        }
        #pragma unroll 8
        for (int k2 = 0; k2 < 64; k2++) {
            float4 p  = *(const float4*)&Ps[k2 * SP + ty * 4];
            float4 vv = *(const float4*)&Vs[k2 * SP + tx * 4];
            acc[0][0] += p.x * vv.x; acc[0][1] += p.x * vv.y;
            acc[0][2] += p.x * vv.z; acc[0][3] += p.x * vv.w;
            acc[1][0] += p.y * vv.x; acc[1][1] += p.y * vv.y;
            acc[1][2] += p.y * vv.z; acc[1][3] += p.y * vv.w;
            acc[2][0] += p.z * vv.x; acc[2][1] += p.z * vv.y;
            acc[2][2] += p.z * vv.z; acc[2][3] += p.z * vv.w;
            acc[3][0] += p.w * vv.x; acc[3][1] += p.w * vv.y;
            acc[3][2] += p.w * vv.z; acc[3][3] += p.w * vv.w;
        }
    }

    #pragma unroll
    for (int i = 0; i < 4; i++) {
        const float inv_l = 1.0f / l_s[ty * 4 + i];
        float4 o;
        o.x = acc[i][0] * inv_l;
        o.y = acc[i][1] * inv_l;
        o.z = acc[i][2] * inv_l;
        o.w = acc[i][3] * inv_l;
        *(float4*)&O[((size_t)(b * SEQ + q0 + ty * 4 + i)) * DM + h * DH + tx * 4] = o;
    }
}

// ---------------------------------------------------------------------------
// Fused residual add + LayerNorm over last dim (1024). One block per row.
// ---------------------------------------------------------------------------
__global__ __launch_bounds__(256) void add_ln(
    const float* __restrict__ X, const float* __restrict__ Y,
    const float* __restrict__ gamma, const float* __restrict__ beta,
    float* __restrict__ out)
{
    __shared__ float red[256];
    const int row = blockIdx.x;
    const int tid = threadIdx.x;
    const float* xp = X + (size_t)row * DM;
    const float* yp = Y + (size_t)row * DM;

    float4 a = *(const float4*)&xp[tid * 4];
    float4 b = *(const float4*)&yp[tid * 4];
    float v0 = a.x + b.x, v1 = a.y + b.y, v2 = a.z + b.z, v3 = a.w + b.w;

    red[tid] = v0 + v1 + v2 + v3;
    __syncthreads();
    for (int o = 128; o > 0; o >>= 1) {
        if (tid < o) red[tid] += red[tid + o];
        __syncthreads();
    }
    const float mean = red[0] * (1.0f / DM);
    __syncthreads();

    v0 -= mean; v1 -= mean; v2 -= mean; v3 -= mean;
    red[tid] = v0 * v0 + v1 * v1 + v2 * v2 + v3 * v3;
    __syncthreads();
    for (int o = 128; o > 0; o >>= 1) {
        if (tid < o) red[tid] += red[tid + o];
        __syncthreads();
    }
    const float rstd = rsqrtf(red[0] * (1.0f / DM) + EPSLN);

    float4 g = *(const float4*)&gamma[tid * 4];
    float4 be = *(const float4*)&beta[tid * 4];
    float4 o4;
    o4.x = v0 * rstd * g.x + be.x;
    o4.y = v1 * rstd * g.y + be.y;
    o4.z = v2 * rstd * g.z + be.z;
    o4.w = v3 * rstd * g.w + be.w;
    *(float4*)&out[(size_t)row * DM + tid * 4] = o4;
}

// ---------------------------------------------------------------------------
#define FLASH_SMEM ((4 * 64 * SP + 3 * 64) * (int)sizeof(float))

extern "C" void kernel_launch(void* const* d_in, const int* in_sizes, int n_in,
                              void* d_out, int out_size)
{
    const float* x   = (const float*)d_in[0];
    const float* Wq  = (const float*)d_in[1];
    const float* bq  = (const float*)d_in[2];
    const float* Wk  = (const float*)d_in[3];
    const float* bk  = (const float*)d_in[4];
    const float* Wv  = (const float*)d_in[5];
    const float* bv  = (const float*)d_in[6];
    const float* Wo  = (const float*)d_in[7];
    const float* bo  = (const float*)d_in[8];
    const float* W1  = (const float*)d_in[9];
    const float* b1  = (const float*)d_in[10];
    const float* W2  = (const float*)d_in[11];
    const float* b2  = (const float*)d_in[12];
    const float* g1  = (const float*)d_in[13];
    const float* be1 = (const float*)d_in[14];
    const float* g2  = (const float*)d_in[15];
    const float* be2 = (const float*)d_in[16];
    float* out = (float*)d_out;

    float *q, *k, *v, *attnc, *tmp, *h, *ff;
    cudaGetSymbolAddress((void**)&q, g_q);
    cudaGetSymbolAddress((void**)&k, g_k);
    cudaGetSymbolAddress((void**)&v, g_v);
    cudaGetSymbolAddress((void**)&attnc, g_attnc);
    cudaGetSymbolAddress((void**)&tmp, g_tmp);
    cudaGetSymbolAddress((void**)&h, g_h);
    cudaGetSymbolAddress((void**)&ff, g_ff);

    __nv_bfloat16 *xh, *xl, *ach, *acl, *hh, *hl, *ffh, *ffl;
    __nv_bfloat16 *Wqh, *Wql, *Wkh, *Wkl, *Wvh, *Wvl, *Woh, *Wol;
    __nv_bfloat16 *W1h, *W1l, *W2h, *W2l;
    cudaGetSymbolAddress((void**)&xh, g_xh);   cudaGetSymbolAddress((void**)&xl, g_xl);
    cudaGetSymbolAddress((void**)&ach, g_ach); cudaGetSymbolAddress((void**)&acl, g_acl);
    cudaGetSymbolAddress((void**)&hh, g_hh);   cudaGetSymbolAddress((void**)&hl, g_hl);
    cudaGetSymbolAddress((void**)&ffh, g_ffh); cudaGetSymbolAddress((void**)&ffl, g_ffl);
    cudaGetSymbolAddress((void**)&Wqh, g_Wqh); cudaGetSymbolAddress((void**)&Wql, g_Wql);
    cudaGetSymbolAddress((void**)&Wkh, g_Wkh); cudaGetSymbolAddress((void**)&Wkl, g_Wkl);
    cudaGetSymbolAddress((void**)&Wvh, g_Wvh); cudaGetSymbolAddress((void**)&Wvl, g_Wvl);
    cudaGetSymbolAddress((void**)&Woh, g_Woh); cudaGetSymbolAddress((void**)&Wol, g_Wol);
    cudaGetSymbolAddress((void**)&W1h, g_W1h); cudaGetSymbolAddress((void**)&W1l, g_W1l);
    cudaGetSymbolAddress((void**)&W2h, g_W2h); cudaGetSymbolAddress((void**)&W2l, g_W2l);

    cudaFuncSetAttribute(flash_attn,
                         cudaFuncAttributeMaxDynamicSharedMemorySize, FLASH_SMEM);

    const int CT = 256;
    #define CONV(src, dh, dl, n) \
        f32_split<<<((n) / 4 + CT - 1) / CT, CT>>>(src, dh, dl, (n) / 4)

    // operand conversions
    CONV(x,  xh,  xl,  TOK * DM);
    CONV(Wq, Wqh, Wql, DM * DM);
    CONV(Wk, Wkh, Wkl, DM * DM);
    CONV(Wv, Wvh, Wvl, DM * DM);
    CONV(Wo, Woh, Wol, DM * DM);
    CONV(W1, W1h, W1l, DFF * DM);
    CONV(W2, W2h, W2l, DM * DFF);

    // QKV projections (tensor-core)
    gemm_mma<<<dim3(DM / BN, TOK / BM), 256>>>(xh, xl, Wqh, Wql, bq, q, TOK, DM, DM, 0);
    gemm_mma<<<dim3(DM / BN, TOK / BM), 256>>>(xh, xl, Wkh, Wkl, bk, k, TOK, DM, DM, 0);
    gemm_mma<<<dim3(DM / BN, TOK / BM), 256>>>(xh, xl, Wvh, Wvl, bv, v, TOK, DM, DM, 0);

    // Attention
    flash_attn<<<dim3(SEQ / 64, 2 * NH), 256, FLASH_SMEM>>>(q, k, v, attnc);

    // Output projection + residual + LN1
    CONV(attnc, ach, acl, TOK * DM);
    gemm_mma<<<dim3(DM / BN, TOK / BM), 256>>>(ach, acl, Woh, Wol, bo, tmp, TOK, DM, DM, 0);
    add_ln<<<TOK, 256>>>(x, tmp, g1, be1, h);

    // FFN
    CONV(h, hh, hl, TOK * DM);
    gemm_mma<<<dim3(DFF / BN, TOK / BM), 256>>>(hh, hl, W1h, W1l, b1, ff, TOK, DFF, DM, 1);
    CONV(ff, ffh, ffl, TOK * DFF);
    gemm_mma<<<dim3(DM / BN, TOK / BM), 256>>>(ffh, ffl, W2h, W2l, b2, tmp, TOK, DM, DFF, 0);

    // Residual + LN2 -> output
    add_ln<<<TOK, 256>>>(h, tmp, g2, be2, out);

    #undef CONV
}

// round 9
// speedup vs baseline: 4.8120x; 1.4578x over previous
#include <cuda_runtime.h>
#include <cuda_bf16.h>
#include <math.h>
#include <stdint.h>

#define TOK   4096          // B*S
#define SEQ   2048
#define DM    1024
#define DFF   4096
#define NH    16
#define DH    64
#define EPSLN 1e-5f

// ---------------- scratch (device globals; no allocation allowed) ----------
__device__ __align__(256) float g_tmp[TOK * DM];
__device__ __align__(256) float g_h[TOK * DM];

__device__ __align__(256) __nv_bfloat16 g_xh[TOK * DM],  g_xl[TOK * DM];
__device__ __align__(256) __nv_bfloat16 g_qh[TOK * DM],  g_ql[TOK * DM];
__device__ __align__(256) __nv_bfloat16 g_kh[TOK * DM],  g_kl[TOK * DM];
__device__ __align__(256) __nv_bfloat16 g_vh[TOK * DM],  g_vl[TOK * DM];
__device__ __align__(256) __nv_bfloat16 g_ach[TOK * DM], g_acl[TOK * DM];
__device__ __align__(256) __nv_bfloat16 g_hh[TOK * DM],  g_hl[TOK * DM];
__device__ __align__(256) __nv_bfloat16 g_ffh[TOK * DFF], g_ffl[TOK * DFF];
__device__ __align__(256) __nv_bfloat16 g_Wqh[DM * DM],  g_Wql[DM * DM];
__device__ __align__(256) __nv_bfloat16 g_Wkh[DM * DM],  g_Wkl[DM * DM];
__device__ __align__(256) __nv_bfloat16 g_Wvh[DM * DM],  g_Wvl[DM * DM];
__device__ __align__(256) __nv_bfloat16 g_Woh[DM * DM],  g_Wol[DM * DM];
__device__ __align__(256) __nv_bfloat16 g_W1h[DFF * DM], g_W1l[DFF * DM];
__device__ __align__(256) __nv_bfloat16 g_W2h[DM * DFF], g_W2l[DM * DFF];

// ---------------------------------------------------------------------------
// helpers
// ---------------------------------------------------------------------------
__device__ __forceinline__ uint32_t smem_u32(const void* p) {
    return (uint32_t)__cvta_generic_to_shared(p);
}
__device__ __forceinline__ void ldsm_x4(uint32_t& r0, uint32_t& r1,
                                        uint32_t& r2, uint32_t& r3, uint32_t a) {
    asm volatile("ldmatrix.sync.aligned.m8n8.x4.shared.b16 {%0,%1,%2,%3}, [%4];"
                 : "=r"(r0), "=r"(r1), "=r"(r2), "=r"(r3) : "r"(a));
}
__device__ __forceinline__ void ldsm_x4_t(uint32_t& r0, uint32_t& r1,
                                          uint32_t& r2, uint32_t& r3, uint32_t a) {
    asm volatile("ldmatrix.sync.aligned.m8n8.x4.trans.shared.b16 {%0,%1,%2,%3}, [%4];"
                 : "=r"(r0), "=r"(r1), "=r"(r2), "=r"(r3) : "r"(a));
}
__device__ __forceinline__ void mma16816(float* c, const uint32_t* a,
                                         const uint32_t* b) {
    asm volatile(
        "mma.sync.aligned.m16n8k16.row.col.f32.bf16.bf16.f32 "
        "{%0,%1,%2,%3}, {%4,%5,%6,%7}, {%8,%9}, {%0,%1,%2,%3};"
        : "+f"(c[0]), "+f"(c[1]), "+f"(c[2]), "+f"(c[3])
        : "r"(a[0]), "r"(a[1]), "r"(a[2]), "r"(a[3]), "r"(b[0]), "r"(b[1]));
}
// split (x,y) into bf16 hi-pair and lo-pair (packed b32, x in low half)
__device__ __forceinline__ void split2(float x, float y, uint32_t& h, uint32_t& l) {
    __nv_bfloat162 h2 = __floats2bfloat162_rn(x, y);
    __nv_bfloat162 l2 = __floats2bfloat162_rn(x - __low2float(h2),
                                              y - __high2float(h2));
    h = *(uint32_t*)&h2;
    l = *(uint32_t*)&l2;
}

// ---------------------------------------------------------------------------
// fp32 -> (bf16 hi, bf16 lo) split conversion. n8 = element_count / 8.
// ---------------------------------------------------------------------------
__global__ __launch_bounds__(256) void f32_split(
    const float* __restrict__ X,
    __nv_bfloat16* __restrict__ H, __nv_bfloat16* __restrict__ L, int n8)
{
    int i = blockIdx.x * blockDim.x + threadIdx.x;
    if (i >= n8) return;
    float4 a = ((const float4*)X)[2 * i];
    float4 b = ((const float4*)X)[2 * i + 1];
    uint4 hv, lv;
    split2(a.x, a.y, hv.x, lv.x);
    split2(a.z, a.w, hv.y, lv.y);
    split2(b.x, b.y, hv.z, lv.z);
    split2(b.z, b.w, hv.w, lv.w);
    ((uint4*)H)[i] = hv;
    ((uint4*)L)[i] = lv;
}

// ---------------------------------------------------------------------------
// Tensor-core GEMM (split-bf16, 3 mma passes): C[M,N] = A[M,K] @ W[N,K]^T + b
// Block tile 128x128, BK=32, 256 thr = 8 warps (4 M x 2 N), warp tile 32x64.
// Epilogue: optional fp32 C, optional split-bf16 (Hh,Hl), optional relu/scale.
// ---------------------------------------------------------------------------
#define BM  128
#define BN  128
#define BKg 32
#define LDSM_STRIDE (BKg + 8)

__global__ __launch_bounds__(256) void gemm_mma(
    const __nv_bfloat16* __restrict__ Ah, const __nv_bfloat16* __restrict__ Al,
    const __nv_bfloat16* __restrict__ Wh, const __nv_bfloat16* __restrict__ Wl,
    const float* __restrict__ bias, float* __restrict__ C,
    __nv_bfloat16* __restrict__ Hh, __nv_bfloat16* __restrict__ Hl,
    int M, int N, int K, int relu, float scale)
{
    __shared__ __nv_bfloat16 Ash[BM][LDSM_STRIDE], Asl[BM][LDSM_STRIDE];
    __shared__ __nv_bfloat16 Wsh[BN][LDSM_STRIDE], Wsl[BN][LDSM_STRIDE];

    const int tid  = threadIdx.x;
    const int lane = tid & 31;
    const int warp = tid >> 5;
    const int wm = (warp >> 1) * 32;
    const int wn = (warp & 1) * 64;
    const int m0 = blockIdx.y * BM;
    const int n0 = blockIdx.x * BN;

    float acc[2][8][4] = {};

    const int a_row = (lane & 15);
    const int a_col = (lane >> 4) << 3;
    const int b_row = ((lane >> 4) << 3) + (lane & 7);
    const int b_col = ((lane >> 3) & 1) << 3;

    for (int kb = 0; kb < K; kb += BKg) {
        #pragma unroll
        for (int i = 0; i < 2; i++) {
            int chunk = tid + i * 256;
            int row = chunk >> 2;
            int c   = chunk & 3;
            const uint4* pa_h = (const uint4*)(Ah + (size_t)(m0 + row) * K + kb) + c;
            const uint4* pa_l = (const uint4*)(Al + (size_t)(m0 + row) * K + kb) + c;
            const uint4* pw_h = (const uint4*)(Wh + (size_t)(n0 + row) * K + kb) + c;
            const uint4* pw_l = (const uint4*)(Wl + (size_t)(n0 + row) * K + kb) + c;
            *(uint4*)&Ash[row][c * 8] = *pa_h;
            *(uint4*)&Asl[row][c * 8] = *pa_l;
            *(uint4*)&Wsh[row][c * 8] = *pw_h;
            *(uint4*)&Wsl[row][c * 8] = *pw_l;
        }
        __syncthreads();

        #pragma unroll
        for (int kk = 0; kk < 2; kk++) {
            uint32_t afh[2][4], afl[2][4];
            #pragma unroll
            for (int mt = 0; mt < 2; mt++) {
                int r = wm + mt * 16 + a_row;
                int c = kk * 16 + a_col;
                ldsm_x4(afh[mt][0], afh[mt][1], afh[mt][2], afh[mt][3],
                        smem_u32(&Ash[r][c]));
                ldsm_x4(afl[mt][0], afl[mt][1], afl[mt][2], afl[mt][3],
                        smem_u32(&Asl[r][c]));
            }
            uint32_t bfh[8][2], bfl[8][2];
            #pragma unroll
            for (int p = 0; p < 4; p++) {
                int r = wn + p * 16 + b_row;
                int c = kk * 16 + b_col;
                uint32_t r0, r1, r2, r3;
                ldsm_x4(r0, r1, r2, r3, smem_u32(&Wsh[r][c]));
                bfh[2 * p][0] = r0; bfh[2 * p][1] = r1;
                bfh[2 * p + 1][0] = r2; bfh[2 * p + 1][1] = r3;
                ldsm_x4(r0, r1, r2, r3, smem_u32(&Wsl[r][c]));
                bfl[2 * p][0] = r0; bfl[2 * p][1] = r1;
                bfl[2 * p + 1][0] = r2; bfl[2 * p + 1][1] = r3;
            }
            #pragma unroll
            for (int mt = 0; mt < 2; mt++)
                #pragma unroll
                for (int nt = 0; nt < 8; nt++) {
                    mma16816(acc[mt][nt], afh[mt], bfh[nt]);
                    mma16816(acc[mt][nt], afh[mt], bfl[nt]);
                    mma16816(acc[mt][nt], afl[mt], bfh[nt]);
                }
        }
        __syncthreads();
    }

    // ---- epilogue
    const int er = lane >> 2;
    const int ec = (lane & 3) * 2;
    #pragma unroll
    for (int mt = 0; mt < 2; mt++) {
        #pragma unroll
        for (int nt = 0; nt < 8; nt++) {
            int row = m0 + wm + mt * 16 + er;
            int col = n0 + wn + nt * 8 + ec;
            float2 b2 = *(const float2*)&bias[col];
            float v0 = acc[mt][nt][0] + b2.x;
            float v1 = acc[mt][nt][1] + b2.y;
            float v2 = acc[mt][nt][2] + b2.x;
            float v3 = acc[mt][nt][3] + b2.y;
            if (relu) {
                v0 = fmaxf(v0, 0.f); v1 = fmaxf(v1, 0.f);
                v2 = fmaxf(v2, 0.f); v3 = fmaxf(v3, 0.f);
            }
            v0 *= scale; v1 *= scale; v2 *= scale; v3 *= scale;
            if (C) {
                *(float2*)&C[(size_t)row * N + col]       = make_float2(v0, v1);
                *(float2*)&C[(size_t)(row + 8) * N + col] = make_float2(v2, v3);
            }
            if (Hh) {
                uint32_t h2, l2;
                split2(v0, v1, h2, l2);
                *(uint32_t*)&Hh[(size_t)row * N + col] = h2;
                *(uint32_t*)&Hl[(size_t)row * N + col] = l2;
                split2(v2, v3, h2, l2);
                *(uint32_t*)&Hh[(size_t)(row + 8) * N + col] = h2;
                *(uint32_t*)&Hl[(size_t)(row + 8) * N + col] = l2;
            }
        }
    }
}

// ---------------------------------------------------------------------------
// Flash attention on tensor cores (split-bf16, 3 mma passes both GEMMs).
// block = 128 thr (4 warps), Q tile 64 (16 rows/warp), K tile 64, dh=64.
// Q is pre-scaled by 1/sqrt(dh) at the QKV GEMM epilogue.
// Output written as split-bf16 (feeds the Wo GEMM directly).
// ---------------------------------------------------------------------------
#define FSP 72   // bf16 row stride: 144B = 9*16B (ldmatrix-aligned, conflict-free)

__global__ __launch_bounds__(128) void flash_mma(
    const __nv_bfloat16* __restrict__ Qh, const __nv_bfloat16* __restrict__ Ql,
    const __nv_bfloat16* __restrict__ Kh, const __nv_bfloat16* __restrict__ Kl,
    const __nv_bfloat16* __restrict__ Vh, const __nv_bfloat16* __restrict__ Vl,
    __nv_bfloat16* __restrict__ Oh, __nv_bfloat16* __restrict__ Ol)
{
    extern __shared__ __nv_bfloat16 smf[];
    __nv_bfloat16* Qsh = smf;               // [64][FSP]
    __nv_bfloat16* Qsl = Qsh + 64 * FSP;
    __nv_bfloat16* Ksh = Qsl + 64 * FSP;
    __nv_bfloat16* Ksl = Ksh + 64 * FSP;
    __nv_bfloat16* Vsh = Ksl + 64 * FSP;
    __nv_bfloat16* Vsl = Vsh + 64 * FSP;

    const int tid  = threadIdx.x;
    const int lane = tid & 31;
    const int warp = tid >> 5;
    const int bh_ = blockIdx.y;
    const int b = bh_ / NH, h = bh_ % NH;
    const int q0 = blockIdx.x * 64;

    // ---- load Q tile [query][dh]
    #pragma unroll
    for (int i = 0; i < 4; i++) {
        int chunk = tid + i * 128;          // 0..511
        int row = chunk >> 3, c = chunk & 7;
        size_t g = (size_t)(b * SEQ + q0 + row) * DM + h * DH;
        *(uint4*)&Qsh[row * FSP + c * 8] = *((const uint4*)(Qh + g) + c);
        *(uint4*)&Qsl[row * FSP + c * 8] = *((const uint4*)(Ql + g) + c);
    }
    __syncthreads();

    // ---- preload Q fragments (A-operand), 4 k-chunks, hi & lo
    const int a_row = lane & 15;
    const int a_col = (lane >> 4) << 3;
    uint32_t qfh[4][4], qfl[4][4];
    #pragma unroll
    for (int kc = 0; kc < 4; kc++) {
        uint32_t ad = smem_u32(&Qsh[(warp * 16 + a_row) * FSP + kc * 16 + a_col]);
        ldsm_x4(qfh[kc][0], qfh[kc][1], qfh[kc][2], qfh[kc][3], ad);
        ad = smem_u32(&Qsl[(warp * 16 + a_row) * FSP + kc * 16 + a_col]);
        ldsm_x4(qfl[kc][0], qfl[kc][1], qfl[kc][2], qfl[kc][3], ad);
    }

    // B-operand coords (non-trans, for K)
    const int b_row = ((lane >> 4) << 3) + (lane & 7);
    const int b_col = ((lane >> 3) & 1) << 3;
    // B-operand coords (trans, for V): group g=lane/8
    const int v_krow = ((lane >> 3) & 1) * 8 + (lane & 7);
    const int v_ncol = (lane >> 4) * 8;

    float o[8][4] = {};
    float m0 = -1e30f, m1 = -1e30f, l0 = 0.f, l1 = 0.f;

    for (int kt = 0; kt < SEQ; kt += 64) {
        __syncthreads();    // previous iteration done reading K/V
        #pragma unroll
        for (int i = 0; i < 4; i++) {
            int chunk = tid + i * 128;
            int row = chunk >> 3, c = chunk & 7;
            size_t g = (size_t)(b * SEQ + kt + row) * DM + h * DH;
            *(uint4*)&Ksh[row * FSP + c * 8] = *((const uint4*)(Kh + g) + c);
            *(uint4*)&Ksl[row * FSP + c * 8] = *((const uint4*)(Kl + g) + c);
            *(uint4*)&Vsh[row * FSP + c * 8] = *((const uint4*)(Vh + g) + c);
            *(uint4*)&Vsl[row * FSP + c * 8] = *((const uint4*)(Vl + g) + c);
        }
        __syncthreads();

        // ---- S = Q @ K^T   (s[nt]: keys nt*8..+7 within this tile)
        float s[8][4] = {};
        #pragma unroll
        for (int kc = 0; kc < 4; kc++) {
            uint32_t kbh[8][2], kbl[8][2];
            #pragma unroll
            for (int p = 0; p < 4; p++) {
                uint32_t r0, r1, r2, r3;
                ldsm_x4(r0, r1, r2, r3,
                        smem_u32(&Ksh[(p * 16 + b_row) * FSP + kc * 16 + b_col]));
                kbh[2 * p][0] = r0; kbh[2 * p][1] = r1;
                kbh[2 * p + 1][0] = r2; kbh[2 * p + 1][1] = r3;
                ldsm_x4(r0, r1, r2, r3,
                        smem_u32(&Ksl[(p * 16 + b_row) * FSP + kc * 16 + b_col]));
                kbl[2 * p][0] = r0; kbl[2 * p][1] = r1;
                kbl[2 * p + 1][0] = r2; kbl[2 * p + 1][1] = r3;
            }
            #pragma unroll
            for (int nt = 0; nt < 8; nt++) {
                mma16816(s[nt], qfh[kc], kbh[nt]);
                mma16816(s[nt], qfh[kc], kbl[nt]);
                mma16816(s[nt], qfl[kc], kbh[nt]);
            }
        }

        // ---- online softmax (rows r=lane/4 and r+8; quad-local reductions)
        float mx0 = -1e30f, mx1 = -1e30f;
        #pragma unroll
        for (int nt = 0; nt < 8; nt++) {
            mx0 = fmaxf(mx0, fmaxf(s[nt][0], s[nt][1]));
            mx1 = fmaxf(mx1, fmaxf(s[nt][2], s[nt][3]));
        }
        mx0 = fmaxf(mx0, __shfl_xor_sync(0xffffffffu, mx0, 1));
        mx0 = fmaxf(mx0, __shfl_xor_sync(0xffffffffu, mx0, 2));
        mx1 = fmaxf(mx1, __shfl_xor_sync(0xffffffffu, mx1, 1));
        mx1 = fmaxf(mx1, __shfl_xor_sync(0xffffffffu, mx1, 2));
        const float mn0 = fmaxf(m0, mx0), mn1 = fmaxf(m1, mx1);
        const float al0 = __expf(m0 - mn0), al1 = __expf(m1 - mn1);
        float sum0 = 0.f, sum1 = 0.f;
        #pragma unroll
        for (int nt = 0; nt < 8; nt++) {
            s[nt][0] = __expf(s[nt][0] - mn0);
            s[nt][1] = __expf(s[nt][1] - mn0);
            s[nt][2] = __expf(s[nt][2] - mn1);
            s[nt][3] = __expf(s[nt][3] - mn1);
            sum0 += s[nt][0] + s[nt][1];
            sum1 += s[nt][2] + s[nt][3];
        }
        sum0 += __shfl_xor_sync(0xffffffffu, sum0, 1);
        sum0 += __shfl_xor_sync(0xffffffffu, sum0, 2);
        sum1 += __shfl_xor_sync(0xffffffffu, sum1, 1);
        sum1 += __shfl_xor_sync(0xffffffffu, sum1, 2);
        l0 = l0 * al0 + sum0;
        l1 = l1 * al1 + sum1;
        m0 = mn0; m1 = mn1;
        #pragma unroll
        for (int nt = 0; nt < 8; nt++) {
            o[nt][0] *= al0; o[nt][1] *= al0;
            o[nt][2] *= al1; o[nt][3] *= al1;
        }

        // ---- O += P @ V
        #pragma unroll
        for (int kc = 0; kc < 4; kc++) {
            // P A-fragments (split): k-chunk kc spans s-tiles 2kc, 2kc+1
            uint32_t aph[4], apl[4];
            split2(s[2 * kc][0],     s[2 * kc][1],     aph[0], apl[0]);
            split2(s[2 * kc][2],     s[2 * kc][3],     aph[1], apl[1]);
            split2(s[2 * kc + 1][0], s[2 * kc + 1][1], aph[2], apl[2]);
            split2(s[2 * kc + 1][2], s[2 * kc + 1][3], aph[3], apl[3]);
            // V B-fragments via trans ldmatrix from [key][dh]
            uint32_t vbh[8][2], vbl[8][2];
            #pragma unroll
            for (int np = 0; np < 4; np++) {
                uint32_t r0, r1, r2, r3;
                ldsm_x4_t(r0, r1, r2, r3,
                          smem_u32(&Vsh[(kc * 16 + v_krow) * FSP + np * 16 + v_ncol]));
                vbh[2 * np][0] = r0; vbh[2 * np][1] = r1;
                vbh[2 * np + 1][0] = r2; vbh[2 * np + 1][1] = r3;
                ldsm_x4_t(r0, r1, r2, r3,
                          smem_u32(&Vsl[(kc * 16 + v_krow) * FSP + np * 16 + v_ncol]));
                vbl[2 * np][0] = r0; vbl[2 * np][1] = r1;
                vbl[2 * np + 1][0] = r2; vbl[2 * np + 1][1] = r3;
            }
            #pragma unroll
            for (int nt = 0; nt < 8; nt++) {
                mma16816(o[nt], aph, vbh[nt]);
                mma16816(o[nt], aph, vbl[nt]);
                mma16816(o[nt], apl, vbh[nt]);
            }
        }
    }

    // ---- epilogue: normalize, split to bf16 hi/lo, concat-heads layout
    const float inv0 = 1.0f / l0, inv1 = 1.0f / l1;
    const int row0 = q0 + warp * 16 + (lane >> 2);
    const int colb = (lane & 3) * 2;
    #pragma unroll
    for (int nt = 0; nt < 8; nt++) {
        size_t i0 = (size_t)(b * SEQ + row0) * DM + h * DH + nt * 8 + colb;
        size_t i1 = i0 + (size_t)8 * DM;
        uint32_t h2, l2;
        split2(o[nt][0] * inv0, o[nt][1] * inv0, h2, l2);
        *(uint32_t*)&Oh[i0] = h2;
        *(uint32_t*)&Ol[i0] = l2;
        split2(o[nt][2] * inv1, o[nt][3] * inv1, h2, l2);
        *(uint32_t*)&Oh[i1] = h2;
        *(uint32_t*)&Ol[i1] = l2;
    }
}

// ---------------------------------------------------------------------------
// Fused residual add + LayerNorm (+ optional split-bf16 output for next GEMM)
// ---------------------------------------------------------------------------
__global__ __launch_bounds__(256) void add_ln(
    const float* __restrict__ X, const float* __restrict__ Y,
    const float* __restrict__ gamma, const float* __restrict__ beta,
    float* __restrict__ out,
    __nv_bfloat16* __restrict__ Hh, __nv_bfloat16* __restrict__ Hl)
{
    __shared__ float red[256];
    const int row = blockIdx.x;
    const int tid = threadIdx.x;
    const float* xp = X + (size_t)row * DM;
    const float* yp = Y + (size_t)row * DM;

    float4 a = *(const float4*)&xp[tid * 4];
    float4 b = *(const float4*)&yp[tid * 4];
    float v0 = a.x + b.x, v1 = a.y + b.y, v2 = a.z + b.z, v3 = a.w + b.w;

    red[tid] = v0 + v1 + v2 + v3;
    __syncthreads();
    for (int o = 128; o > 0; o >>= 1) {
        if (tid < o) red[tid] += red[tid + o];
        __syncthreads();
    }
    const float mean = red[0] * (1.0f / DM);
    __syncthreads();

    v0 -= mean; v1 -= mean; v2 -= mean; v3 -= mean;
    red[tid] = v0 * v0 + v1 * v1 + v2 * v2 + v3 * v3;
    __syncthreads();
    for (int o = 128; o > 0; o >>= 1) {
        if (tid < o) red[tid] += red[tid + o];
        __syncthreads();
    }
    const float rstd = rsqrtf(red[0] * (1.0f / DM) + EPSLN);

    float4 g = *(const float4*)&gamma[tid * 4];
    float4 be = *(const float4*)&beta[tid * 4];
    float o0 = v0 * rstd * g.x + be.x;
    float o1 = v1 * rstd * g.y + be.y;
    float o2 = v2 * rstd * g.z + be.z;
    float o3 = v3 * rstd * g.w + be.w;
    float4 o4 = make_float4(o0, o1, o2, o3);
    *(float4*)&out[(size_t)row * DM + tid * 4] = o4;

    if (Hh) {
        uint2 hp, lp;
        split2(o0, o1, hp.x, lp.x);
        split2(o2, o3, hp.y, lp.y);
        *(uint2*)&Hh[(size_t)row * DM + tid * 4] = hp;
        *(uint2*)&Hl[(size_t)row * DM + tid * 4] = lp;
    }
}

// ---------------------------------------------------------------------------
#define FL_SMEM (6 * 64 * FSP * (int)sizeof(__nv_bfloat16))

extern "C" void kernel_launch(void* const* d_in, const int* in_sizes, int n_in,
                              void* d_out, int out_size)
{
    const float* x   = (const float*)d_in[0];
    const float* Wq  = (const float*)d_in[1];
    const float* bq  = (const float*)d_in[2];
    const float* Wk  = (const float*)d_in[3];
    const float* bk  = (const float*)d_in[4];
    const float* Wv  = (const float*)d_in[5];
    const float* bv  = (const float*)d_in[6];
    const float* Wo  = (const float*)d_in[7];
    const float* bo  = (const float*)d_in[8];
    const float* W1  = (const float*)d_in[9];
    const float* b1  = (const float*)d_in[10];
    const float* W2  = (const float*)d_in[11];
    const float* b2  = (const float*)d_in[12];
    const float* g1  = (const float*)d_in[13];
    const float* be1 = (const float*)d_in[14];
    const float* g2  = (const float*)d_in[15];
    const float* be2 = (const float*)d_in[16];
    float* out = (float*)d_out;

    float *tmp, *h;
    cudaGetSymbolAddress((void**)&tmp, g_tmp);
    cudaGetSymbolAddress((void**)&h, g_h);

    __nv_bfloat16 *xh, *xl, *qh, *ql, *kh, *kl, *vh, *vl;
    __nv_bfloat16 *ach, *acl, *hh, *hl, *ffh, *ffl;
    __nv_bfloat16 *Wqh, *Wql, *Wkh, *Wkl, *Wvh, *Wvl, *Woh, *Wol;
    __nv_bfloat16 *W1h, *W1l, *W2h, *W2l;
    cudaGetSymbolAddress((void**)&xh, g_xh);   cudaGetSymbolAddress((void**)&xl, g_xl);
    cudaGetSymbolAddress((void**)&qh, g_qh);   cudaGetSymbolAddress((void**)&ql, g_ql);
    cudaGetSymbolAddress((void**)&kh, g_kh);   cudaGetSymbolAddress((void**)&kl, g_kl);
    cudaGetSymbolAddress((void**)&vh, g_vh);   cudaGetSymbolAddress((void**)&vl, g_vl);
    cudaGetSymbolAddress((void**)&ach, g_ach); cudaGetSymbolAddress((void**)&acl, g_acl);
    cudaGetSymbolAddress((void**)&hh, g_hh);   cudaGetSymbolAddress((void**)&hl, g_hl);
    cudaGetSymbolAddress((void**)&ffh, g_ffh); cudaGetSymbolAddress((void**)&ffl, g_ffl);
    cudaGetSymbolAddress((void**)&Wqh, g_Wqh); cudaGetSymbolAddress((void**)&Wql, g_Wql);
    cudaGetSymbolAddress((void**)&Wkh, g_Wkh); cudaGetSymbolAddress((void**)&Wkl, g_Wkl);
    cudaGetSymbolAddress((void**)&Wvh, g_Wvh); cudaGetSymbolAddress((void**)&Wvl, g_Wvl);
    cudaGetSymbolAddress((void**)&Woh, g_Woh); cudaGetSymbolAddress((void**)&Wol, g_Wol);
    cudaGetSymbolAddress((void**)&W1h, g_W1h); cudaGetSymbolAddress((void**)&W1l, g_W1l);
    cudaGetSymbolAddress((void**)&W2h, g_W2h); cudaGetSymbolAddress((void**)&W2l, g_W2l);

    cudaFuncSetAttribute(flash_mma,
                         cudaFuncAttributeMaxDynamicSharedMemorySize, FL_SMEM);

    const int CT = 256;
    #define CONV(src, dh, dl, n) \
        f32_split<<<((n) / 8 + CT - 1) / CT, CT>>>(src, dh, dl, (n) / 8)

    // standalone conversions: input x + the 6 weights
    CONV(x,  xh,  xl,  TOK * DM);
    CONV(Wq, Wqh, Wql, DM * DM);
    CONV(Wk, Wkh, Wkl, DM * DM);
    CONV(Wv, Wvh, Wvl, DM * DM);
    CONV(Wo, Woh, Wol, DM * DM);
    CONV(W1, W1h, W1l, DFF * DM);
    CONV(W2, W2h, W2l, DM * DFF);

    // QKV projections -> split-bf16 directly (Q pre-scaled by 1/sqrt(dh))
    gemm_mma<<<dim3(DM / BN, TOK / BM), 256>>>(xh, xl, Wqh, Wql, bq,
        nullptr, qh, ql, TOK, DM, DM, 0, 0.125f);
    gemm_mma<<<dim3(DM / BN, TOK / BM), 256>>>(xh, xl, Wkh, Wkl, bk,
        nullptr, kh, kl, TOK, DM, DM, 0, 1.0f);
    gemm_mma<<<dim3(DM / BN, TOK / BM), 256>>>(xh, xl, Wvh, Wvl, bv,
        nullptr, vh, vl, TOK, DM, DM, 0, 1.0f);

    // Attention (tensor cores) -> split-bf16 concat-heads output
    flash_mma<<<dim3(SEQ / 64, 2 * NH), 128, FL_SMEM>>>(qh, ql, kh, kl, vh, vl,
                                                        ach, acl);

    // Output projection (fp32 out) + residual + LN1 (fp32 h + split for FFN)
    gemm_mma<<<dim3(DM / BN, TOK / BM), 256>>>(ach, acl, Woh, Wol, bo,
        tmp, nullptr, nullptr, TOK, DM, DM, 0, 1.0f);
    add_ln<<<TOK, 256>>>(x, tmp, g1, be1, h, hh, hl);

    // FFN: W1 (+ReLU) -> split-bf16 only; W2 -> fp32
    gemm_mma<<<dim3(DFF / BN, TOK / BM), 256>>>(hh, hl, W1h, W1l, b1,
        nullptr, ffh, ffl, TOK, DFF, DM, 1, 1.0f);
    gemm_mma<<<dim3(DM / BN, TOK / BM), 256>>>(ffh, ffl, W2h, W2l, b2,
        tmp, nullptr, nullptr, TOK, DM, DFF, 0, 1.0f);

    // Residual + LN2 -> output
    add_ln<<<TOK, 256>>>(h, tmp, g2, be2, out, nullptr, nullptr);

    #undef CONV
}

// round 10
// speedup vs baseline: 4.9372x; 1.0260x over previous
#include <cuda_runtime.h>
#include <cuda_bf16.h>
#include <math.h>
#include <stdint.h>

#define TOK   4096          // B*S
#define SEQ   2048
#define DM    1024
#define DFF   4096
#define NH    16
#define DH    64
#define EPSLN 1e-5f

// ---------------- scratch (device globals; no allocation allowed) ----------
__device__ __align__(256) float g_tmp[TOK * DM];
__device__ __align__(256) float g_h[TOK * DM];

__device__ __align__(256) __nv_bfloat16 g_xh[TOK * DM],  g_xl[TOK * DM];
__device__ __align__(256) __nv_bfloat16 g_qh[TOK * DM],  g_ql[TOK * DM];
__device__ __align__(256) __nv_bfloat16 g_kh[TOK * DM],  g_kl[TOK * DM];
__device__ __align__(256) __nv_bfloat16 g_vh[TOK * DM],  g_vl[TOK * DM];
__device__ __align__(256) __nv_bfloat16 g_ach[TOK * DM], g_acl[TOK * DM];
__device__ __align__(256) __nv_bfloat16 g_hh[TOK * DM],  g_hl[TOK * DM];
__device__ __align__(256) __nv_bfloat16 g_ffh[TOK * DFF], g_ffl[TOK * DFF];
__device__ __align__(256) __nv_bfloat16 g_Wqh[DM * DM],  g_Wql[DM * DM];
__device__ __align__(256) __nv_bfloat16 g_Wkh[DM * DM],  g_Wkl[DM * DM];
__device__ __align__(256) __nv_bfloat16 g_Wvh[DM * DM],  g_Wvl[DM * DM];
__device__ __align__(256) __nv_bfloat16 g_Woh[DM * DM],  g_Wol[DM * DM];
__device__ __align__(256) __nv_bfloat16 g_W1h[DFF * DM], g_W1l[DFF * DM];
__device__ __align__(256) __nv_bfloat16 g_W2h[DM * DFF], g_W2l[DM * DFF];

// ---------------------------------------------------------------------------
// helpers
// ---------------------------------------------------------------------------
__device__ __forceinline__ uint32_t smem_u32(const void* p) {
    return (uint32_t)__cvta_generic_to_shared(p);
}
__device__ __forceinline__ void cp16(uint32_t dst, const void* src) {
    asm volatile("cp.async.cg.shared.global [%0], [%1], 16;"
                 :: "r"(dst), "l"(src) : "memory");
}
#define CP_COMMIT() asm volatile("cp.async.commit_group;" ::: "memory")
#define CP_WAIT1()  asm volatile("cp.async.wait_group 1;" ::: "memory")
#define CP_WAIT0()  asm volatile("cp.async.wait_group 0;" ::: "memory")

__device__ __forceinline__ void ldsm_x4(uint32_t& r0, uint32_t& r1,
                                        uint32_t& r2, uint32_t& r3, uint32_t a) {
    asm volatile("ldmatrix.sync.aligned.m8n8.x4.shared.b16 {%0,%1,%2,%3}, [%4];"
                 : "=r"(r0), "=r"(r1), "=r"(r2), "=r"(r3) : "r"(a));
}
__device__ __forceinline__ void ldsm_x4_t(uint32_t& r0, uint32_t& r1,
                                          uint32_t& r2, uint32_t& r3, uint32_t a) {
    asm volatile("ldmatrix.sync.aligned.m8n8.x4.trans.shared.b16 {%0,%1,%2,%3}, [%4];"
                 : "=r"(r0), "=r"(r1), "=r"(r2), "=r"(r3) : "r"(a));
}
__device__ __forceinline__ void mma16816(float* c, const uint32_t* a,
                                         const uint32_t* b) {
    asm volatile(
        "mma.sync.aligned.m16n8k16.row.col.f32.bf16.bf16.f32 "
        "{%0,%1,%2,%3}, {%4,%5,%6,%7}, {%8,%9}, {%0,%1,%2,%3};"
        : "+f"(c[0]), "+f"(c[1]), "+f"(c[2]), "+f"(c[3])
        : "r"(a[0]), "r"(a[1]), "r"(a[2]), "r"(a[3]), "r"(b[0]), "r"(b[1]));
}
__device__ __forceinline__ void split2(float x, float y, uint32_t& h, uint32_t& l) {
    __nv_bfloat162 h2 = __floats2bfloat162_rn(x, y);
    __nv_bfloat162 l2 = __floats2bfloat162_rn(x - __low2float(h2),
                                              y - __high2float(h2));
    h = *(uint32_t*)&h2;
    l = *(uint32_t*)&l2;
}

// ---------------------------------------------------------------------------
// fp32 -> (bf16 hi, bf16 lo) split conversion. n8 = element_count / 8.
// ---------------------------------------------------------------------------
__global__ __launch_bounds__(256) void f32_split(
    const float* __restrict__ X,
    __nv_bfloat16* __restrict__ H, __nv_bfloat16* __restrict__ L, int n8)
{
    int i = blockIdx.x * blockDim.x + threadIdx.x;
    if (i >= n8) return;
    float4 a = ((const float4*)X)[2 * i];
    float4 b = ((const float4*)X)[2 * i + 1];
    uint4 hv, lv;
    split2(a.x, a.y, hv.x, lv.x);
    split2(a.z, a.w, hv.y, lv.y);
    split2(b.x, b.y, hv.z, lv.z);
    split2(b.z, b.w, hv.w, lv.w);
    ((uint4*)H)[i] = hv;
    ((uint4*)L)[i] = lv;
}

// ---------------------------------------------------------------------------
// Tensor-core GEMM (split-bf16, 3 mma passes): C[M,N] = A[M,K] @ W[N,K]^T + b
// Block tile 128x128, BK=32, 256 thr = 8 warps (4 M x 2 N), warp tile 32x64.
// 2-stage cp.async double buffer. Dynamic smem 80KB.
// ---------------------------------------------------------------------------
#define BM  128
#define BN  128
#define BKg 32
#define LDSM_STRIDE (BKg + 8)
#define GT   (BM * LDSM_STRIDE)     // one tile array (elems)
#define GSTG (4 * GT)               // one stage: Ash,Asl,Wsh,Wsl
#define GEMM_SMEM (2 * GSTG * (int)sizeof(__nv_bfloat16))

__global__ __launch_bounds__(256) void gemm_mma(
    const __nv_bfloat16* __restrict__ Ah, const __nv_bfloat16* __restrict__ Al,
    const __nv_bfloat16* __restrict__ Wh, const __nv_bfloat16* __restrict__ Wl,
    const float* __restrict__ bias, float* __restrict__ C,
    __nv_bfloat16* __restrict__ Hh, __nv_bfloat16* __restrict__ Hl,
    int M, int N, int K, int relu, float scale)
{
    extern __shared__ __nv_bfloat16 gsm[];

    const int tid  = threadIdx.x;
    const int lane = tid & 31;
    const int warp = tid >> 5;
    const int wm = (warp >> 1) * 32;
    const int wn = (warp & 1) * 64;
    const int m0 = blockIdx.y * BM;
    const int n0 = blockIdx.x * BN;

    float acc[2][8][4] = {};

    const int a_row = (lane & 15);
    const int a_col = (lane >> 4) << 3;
    const int b_row = ((lane >> 4) << 3) + (lane & 7);
    const int b_col = ((lane >> 3) & 1) << 3;

    // ---- async tile loader (issues 8 cp.async per thread + commit)
    auto load_tiles = [&](int kb, int stage) {
        __nv_bfloat16* As_h = gsm + stage * GSTG;
        __nv_bfloat16* As_l = As_h + GT;
        __nv_bfloat16* Ws_h = As_l + GT;
        __nv_bfloat16* Ws_l = Ws_h + GT;
        #pragma unroll
        for (int i = 0; i < 2; i++) {
            int chunk = tid + i * 256;
            int row = chunk >> 2;
            int c   = chunk & 3;
            size_t ga = (size_t)(m0 + row) * K + kb + c * 8;
            size_t gw = (size_t)(n0 + row) * K + kb + c * 8;
            uint32_t so = (uint32_t)(row * LDSM_STRIDE + c * 8);
            cp16(smem_u32(As_h + so), Ah + ga);
            cp16(smem_u32(As_l + so), Al + ga);
            cp16(smem_u32(Ws_h + so), Wh + gw);
            cp16(smem_u32(Ws_l + so), Wl + gw);
        }
        CP_COMMIT();
    };

    auto compute = [&](int stage) {
        const __nv_bfloat16* As_h = gsm + stage * GSTG;
        const __nv_bfloat16* As_l = As_h + GT;
        const __nv_bfloat16* Ws_h = As_l + GT;
        const __nv_bfloat16* Ws_l = Ws_h + GT;
        #pragma unroll
        for (int kk = 0; kk < 2; kk++) {
            uint32_t afh[2][4], afl[2][4];
            #pragma unroll
            for (int mt = 0; mt < 2; mt++) {
                int r = wm + mt * 16 + a_row;
                int c = kk * 16 + a_col;
                ldsm_x4(afh[mt][0], afh[mt][1], afh[mt][2], afh[mt][3],
                        smem_u32(As_h + r * LDSM_STRIDE + c));
                ldsm_x4(afl[mt][0], afl[mt][1], afl[mt][2], afl[mt][3],
                        smem_u32(As_l + r * LDSM_STRIDE + c));
            }
            uint32_t bfh[8][2], bfl[8][2];
            #pragma unroll
            for (int p = 0; p < 4; p++) {
                int r = wn + p * 16 + b_row;
                int c = kk * 16 + b_col;
                uint32_t r0, r1, r2, r3;
                ldsm_x4(r0, r1, r2, r3, smem_u32(Ws_h + r * LDSM_STRIDE + c));
                bfh[2 * p][0] = r0; bfh[2 * p][1] = r1;
                bfh[2 * p + 1][0] = r2; bfh[2 * p + 1][1] = r3;
                ldsm_x4(r0, r1, r2, r3, smem_u32(Ws_l + r * LDSM_STRIDE + c));
                bfl[2 * p][0] = r0; bfl[2 * p][1] = r1;
                bfl[2 * p + 1][0] = r2; bfl[2 * p + 1][1] = r3;
            }
            #pragma unroll
            for (int mt = 0; mt < 2; mt++)
                #pragma unroll
                for (int nt = 0; nt < 8; nt++) {
                    mma16816(acc[mt][nt], afh[mt], bfh[nt]);
                    mma16816(acc[mt][nt], afh[mt], bfl[nt]);
                    mma16816(acc[mt][nt], afl[mt], bfh[nt]);
                }
        }
    };

    const int nk = K / BKg;        // >= 32 for all our shapes
    load_tiles(0, 0);
    load_tiles(BKg, 1);
    for (int it = 0; it < nk; it++) {
        if (it < nk - 1) { CP_WAIT1(); } else { CP_WAIT0(); }
        __syncthreads();
        compute(it & 1);
        __syncthreads();
        if (it + 2 < nk) load_tiles((it + 2) * BKg, it & 1);
    }

    // ---- epilogue
    const int er = lane >> 2;
    const int ec = (lane & 3) * 2;
    #pragma unroll
    for (int mt = 0; mt < 2; mt++) {
        #pragma unroll
        for (int nt = 0; nt < 8; nt++) {
            int row = m0 + wm + mt * 16 + er;
            int col = n0 + wn + nt * 8 + ec;
            float2 b2 = *(const float2*)&bias[col];
            float v0 = acc[mt][nt][0] + b2.x;
            float v1 = acc[mt][nt][1] + b2.y;
            float v2 = acc[mt][nt][2] + b2.x;
            float v3 = acc[mt][nt][3] + b2.y;
            if (relu) {
                v0 = fmaxf(v0, 0.f); v1 = fmaxf(v1, 0.f);
                v2 = fmaxf(v2, 0.f); v3 = fmaxf(v3, 0.f);
            }
            v0 *= scale; v1 *= scale; v2 *= scale; v3 *= scale;
            if (C) {
                *(float2*)&C[(size_t)row * N + col]       = make_float2(v0, v1);
                *(float2*)&C[(size_t)(row + 8) * N + col] = make_float2(v2, v3);
            }
            if (Hh) {
                uint32_t h2, l2;
                split2(v0, v1, h2, l2);
                *(uint32_t*)&Hh[(size_t)row * N + col] = h2;
                *(uint32_t*)&Hl[(size_t)row * N + col] = l2;
                split2(v2, v3, h2, l2);
                *(uint32_t*)&Hh[(size_t)(row + 8) * N + col] = h2;
                *(uint32_t*)&Hl[(size_t)(row + 8) * N + col] = l2;
            }
        }
    }
}

// ---------------------------------------------------------------------------
// Flash attention on tensor cores (split-bf16, 3 mma passes both GEMMs).
// block = 256 thr (8 warps), Q tile 128 (16 rows/warp), K tile 64, dh=64.
// 2-stage cp.async K/V pipeline. Q pre-scaled by 1/sqrt(dh) at QKV epilogue.
// ---------------------------------------------------------------------------
#define FSP   72                 // bf16 row stride (144B = 9*16B)
#define QT    128
#define FQ    (QT * FSP)         // one Q array
#define KVT   (64 * FSP)         // one K/V array
#define KVSTG (4 * KVT)          // one stage: Ksh,Ksl,Vsh,Vsl
#define FL_SMEM ((2 * FQ + 2 * KVSTG) * (int)sizeof(__nv_bfloat16))

__global__ __launch_bounds__(256) void flash_mma(
    const __nv_bfloat16* __restrict__ Qh, const __nv_bfloat16* __restrict__ Ql,
    const __nv_bfloat16* __restrict__ Kh, const __nv_bfloat16* __restrict__ Kl,
    const __nv_bfloat16* __restrict__ Vh, const __nv_bfloat16* __restrict__ Vl,
    __nv_bfloat16* __restrict__ Oh, __nv_bfloat16* __restrict__ Ol)
{
    extern __shared__ __nv_bfloat16 smf[];
    __nv_bfloat16* Qsh = smf;
    __nv_bfloat16* Qsl = Qsh + FQ;
    __nv_bfloat16* KV0 = Qsl + FQ;     // stage base

    const int tid  = threadIdx.x;
    const int lane = tid & 31;
    const int warp = tid >> 5;
    const int bh_ = blockIdx.y;
    const int b = bh_ / NH, h = bh_ % NH;
    const int q0 = blockIdx.x * QT;

    // ---- async K/V tile loader for one 64-key stage
    auto load_kv = [&](int kt, int stage) {
        __nv_bfloat16* Ksh = KV0 + stage * KVSTG;
        __nv_bfloat16* Ksl = Ksh + KVT;
        __nv_bfloat16* Vsh = Ksl + KVT;
        __nv_bfloat16* Vsl = Vsh + KVT;
        #pragma unroll
        for (int i = 0; i < 2; i++) {
            int chunk = tid + i * 256;      // 0..511
            int row = chunk >> 3, c = chunk & 7;
            size_t g = (size_t)(b * SEQ + kt + row) * DM + h * DH + c * 8;
            uint32_t so = (uint32_t)(row * FSP + c * 8);
            cp16(smem_u32(Ksh + so), Kh + g);
            cp16(smem_u32(Ksl + so), Kl + g);
            cp16(smem_u32(Vsh + so), Vh + g);
            cp16(smem_u32(Vsl + so), Vl + g);
        }
        CP_COMMIT();
    };

    // prologue: start K/V stages 0 and 1 flying, then load Q (regular)
    load_kv(0, 0);
    load_kv(64, 1);
    #pragma unroll
    for (int i = 0; i < 4; i++) {
        int chunk = tid + i * 256;          // 0..1023
        int row = chunk >> 3, c = chunk & 7;
        size_t g = (size_t)(b * SEQ + q0 + row) * DM + h * DH;
        *(uint4*)&Qsh[row * FSP + c * 8] = *((const uint4*)(Qh + g) + c);
        *(uint4*)&Qsl[row * FSP + c * 8] = *((const uint4*)(Ql + g) + c);
    }
    __syncthreads();

    // ---- preload Q fragments (A-operand), 4 k-chunks, hi & lo
    const int a_row = lane & 15;
    const int a_col = (lane >> 4) << 3;
    uint32_t qfh[4][4], qfl[4][4];
    #pragma unroll
    for (int kc = 0; kc < 4; kc++) {
        uint32_t ad = smem_u32(&Qsh[(warp * 16 + a_row) * FSP + kc * 16 + a_col]);
        ldsm_x4(qfh[kc][0], qfh[kc][1], qfh[kc][2], qfh[kc][3], ad);
        ad = smem_u32(&Qsl[(warp * 16 + a_row) * FSP + kc * 16 + a_col]);
        ldsm_x4(qfl[kc][0], qfl[kc][1], qfl[kc][2], qfl[kc][3], ad);
    }

    const int b_row = ((lane >> 4) << 3) + (lane & 7);
    const int b_col = ((lane >> 3) & 1) << 3;
    const int v_krow = ((lane >> 3) & 1) * 8 + (lane & 7);
    const int v_ncol = (lane >> 4) * 8;

    float o[8][4] = {};
    float m0 = -1e30f, m1 = -1e30f, l0 = 0.f, l1 = 0.f;

    const int NT = SEQ / 64;    // 32
    for (int it = 0; it < NT; it++) {
        if (it < NT - 1) { CP_WAIT1(); } else { CP_WAIT0(); }
        __syncthreads();

        const __nv_bfloat16* Ksh = KV0 + (it & 1) * KVSTG;
        const __nv_bfloat16* Ksl = Ksh + KVT;
        const __nv_bfloat16* Vsh = Ksl + KVT;
        const __nv_bfloat16* Vsl = Vsh + KVT;

        // ---- S = Q @ K^T
        float s[8][4] = {};
        #pragma unroll
        for (int kc = 0; kc < 4; kc++) {
            uint32_t kbh[8][2], kbl[8][2];
            #pragma unroll
            for (int p = 0; p < 4; p++) {
                uint32_t r0, r1, r2, r3;
                ldsm_x4(r0, r1, r2, r3,
                        smem_u32(Ksh + (p * 16 + b_row) * FSP + kc * 16 + b_col));
                kbh[2 * p][0] = r0; kbh[2 * p][1] = r1;
                kbh[2 * p + 1][0] = r2; kbh[2 * p + 1][1] = r3;
                ldsm_x4(r0, r1, r2, r3,
                        smem_u32(Ksl + (p * 16 + b_row) * FSP + kc * 16 + b_col));
                kbl[2 * p][0] = r0; kbl[2 * p][1] = r1;
                kbl[2 * p + 1][0] = r2; kbl[2 * p + 1][1] = r3;
            }
            #pragma unroll
            for (int nt = 0; nt < 8; nt++) {
                mma16816(s[nt], qfh[kc], kbh[nt]);
                mma16816(s[nt], qfh[kc], kbl[nt]);
                mma16816(s[nt], qfl[kc], kbh[nt]);
            }
        }

        // ---- online softmax (rows r=lane/4 and r+8; quad reductions)
        float mx0 = -1e30f, mx1 = -1e30f;
        #pragma unroll
        for (int nt = 0; nt < 8; nt++) {
            mx0 = fmaxf(mx0, fmaxf(s[nt][0], s[nt][1]));
            mx1 = fmaxf(mx1, fmaxf(s[nt][2], s[nt][3]));
        }
        mx0 = fmaxf(mx0, __shfl_xor_sync(0xffffffffu, mx0, 1));
        mx0 = fmaxf(mx0, __shfl_xor_sync(0xffffffffu, mx0, 2));
        mx1 = fmaxf(mx1, __shfl_xor_sync(0xffffffffu, mx1, 1));
        mx1 = fmaxf(mx1, __shfl_xor_sync(0xffffffffu, mx1, 2));
        const float mn0 = fmaxf(m0, mx0), mn1 = fmaxf(m1, mx1);
        const float al0 = __expf(m0 - mn0), al1 = __expf(m1 - mn1);
        float sum0 = 0.f, sum1 = 0.f;
        #pragma unroll
        for (int nt = 0; nt < 8; nt++) {
            s[nt][0] = __expf(s[nt][0] - mn0);
            s[nt][1] = __expf(s[nt][1] - mn0);
            s[nt][2] = __expf(s[nt][2] - mn1);
            s[nt][3] = __expf(s[nt][3] - mn1);
            sum0 += s[nt][0] + s[nt][1];
            sum1 += s[nt][2] + s[nt][3];
        }
        sum0 += __shfl_xor_sync(0xffffffffu, sum0, 1);
        sum0 += __shfl_xor_sync(0xffffffffu, sum0, 2);
        sum1 += __shfl_xor_sync(0xffffffffu, sum1, 1);
        sum1 += __shfl_xor_sync(0xffffffffu, sum1, 2);
        l0 = l0 * al0 + sum0;
        l1 = l1 * al1 + sum1;
        m0 = mn0; m1 = mn1;
        #pragma unroll
        for (int nt = 0; nt < 8; nt++) {
            o[nt][0] *= al0; o[nt][1] *= al0;
            o[nt][2] *= al1; o[nt][3] *= al1;
        }

        // ---- O += P @ V
        #pragma unroll
        for (int kc = 0; kc < 4; kc++) {
            uint32_t aph[4], apl[4];
            split2(s[2 * kc][0],     s[2 * kc][1],     aph[0], apl[0]);
            split2(s[2 * kc][2],     s[2 * kc][3],     aph[1], apl[1]);
            split2(s[2 * kc + 1][0], s[2 * kc + 1][1], aph[2], apl[2]);
            split2(s[2 * kc + 1][2], s[2 * kc + 1][3], aph[3], apl[3]);
            uint32_t vbh[8][2], vbl[8][2];
            #pragma unroll
            for (int np = 0; np < 4; np++) {
                uint32_t r0, r1, r2, r3;
                ldsm_x4_t(r0, r1, r2, r3,
                          smem_u32(Vsh + (kc * 16 + v_krow) * FSP + np * 16 + v_ncol));
                vbh[2 * np][0] = r0; vbh[2 * np][1] = r1;
                vbh[2 * np + 1][0] = r2; vbh[2 * np + 1][1] = r3;
                ldsm_x4_t(r0, r1, r2, r3,
                          smem_u32(Vsl + (kc * 16 + v_krow) * FSP + np * 16 + v_ncol));
                vbl[2 * np][0] = r0; vbl[2 * np][1] = r1;
                vbl[2 * np + 1][0] = r2; vbl[2 * np + 1][1] = r3;
            }
            #pragma unroll
            for (int nt = 0; nt < 8; nt++) {
                mma16816(o[nt], aph, vbh[nt]);
                mma16816(o[nt], aph, vbl[nt]);
                mma16816(o[nt], apl, vbh[nt]);
            }
        }

        __syncthreads();
        if (it + 2 < NT) load_kv((it + 2) * 64, it & 1);
    }

    // ---- epilogue: normalize, split to bf16 hi/lo, concat-heads layout
    const float inv0 = 1.0f / l0, inv1 = 1.0f / l1;
    const int row0 = q0 + warp * 16 + (lane >> 2);
    const int colb = (lane & 3) * 2;
    #pragma unroll
    for (int nt = 0; nt < 8; nt++) {
        size_t i0 = (size_t)(b * SEQ + row0) * DM + h * DH + nt * 8 + colb;
        size_t i1 = i0 + (size_t)8 * DM;
        uint32_t h2, l2;
        split2(o[nt][0] * inv0, o[nt][1] * inv0, h2, l2);
        *(uint32_t*)&Oh[i0] = h2;
        *(uint32_t*)&Ol[i0] = l2;
        split2(o[nt][2] * inv1, o[nt][3] * inv1, h2, l2);
        *(uint32_t*)&Oh[i1] = h2;
        *(uint32_t*)&Ol[i1] = l2;
    }
}

// ---------------------------------------------------------------------------
// Fused residual add + LayerNorm (+ optional split-bf16 output for next GEMM)
// ---------------------------------------------------------------------------
__global__ __launch_bounds__(256) void add_ln(
    const float* __restrict__ X, const float* __restrict__ Y,
    const float* __restrict__ gamma, const float* __restrict__ beta,
    float* __restrict__ out,
    __nv_bfloat16* __restrict__ Hh, __nv_bfloat16* __restrict__ Hl)
{
    __shared__ float red[256];
    const int row = blockIdx.x;
    const int tid = threadIdx.x;
    const float* xp = X + (size_t)row * DM;
    const float* yp = Y + (size_t)row * DM;

    float4 a = *(const float4*)&xp[tid * 4];
    float4 b = *(const float4*)&yp[tid * 4];
    float v0 = a.x + b.x, v1 = a.y + b.y, v2 = a.z + b.z, v3 = a.w + b.w;

    red[tid] = v0 + v1 + v2 + v3;
    __syncthreads();
    for (int o = 128; o > 0; o >>= 1) {
        if (tid < o) red[tid] += red[tid + o];
        __syncthreads();
    }
    const float mean = red[0] * (1.0f / DM);
    __syncthreads();

    v0 -= mean; v1 -= mean; v2 -= mean; v3 -= mean;
    red[tid] = v0 * v0 + v1 * v1 + v2 * v2 + v3 * v3;
    __syncthreads();
    for (int o = 128; o > 0; o >>= 1) {
        if (tid < o) red[tid] += red[tid + o];
        __syncthreads();
    }
    const float rstd = rsqrtf(red[0] * (1.0f / DM) + EPSLN);

    float4 g = *(const float4*)&gamma[tid * 4];
    float4 be = *(const float4*)&beta[tid * 4];
    float o0 = v0 * rstd * g.x + be.x;
    float o1 = v1 * rstd * g.y + be.y;
    float o2 = v2 * rstd * g.z + be.z;
    float o3 = v3 * rstd * g.w + be.w;
    float4 o4 = make_float4(o0, o1, o2, o3);
    *(float4*)&out[(size_t)row * DM + tid * 4] = o4;

    if (Hh) {
        uint2 hp, lp;
        split2(o0, o1, hp.x, lp.x);
        split2(o2, o3, hp.y, lp.y);
        *(uint2*)&Hh[(size_t)row * DM + tid * 4] = hp;
        *(uint2*)&Hl[(size_t)row * DM + tid * 4] = lp;
    }
}

// ---------------------------------------------------------------------------
extern "C" void kernel_launch(void* const* d_in, const int* in_sizes, int n_in,
                              void* d_out, int out_size)
{
    const float* x   = (const float*)d_in[0];
    const float* Wq  = (const float*)d_in[1];
    const float* bq  = (const float*)d_in[2];
    const float* Wk  = (const float*)d_in[3];
    const float* bk  = (const float*)d_in[4];
    const float* Wv  = (const float*)d_in[5];
    const float* bv  = (const float*)d_in[6];
    const float* Wo  = (const float*)d_in[7];
    const float* bo  = (const float*)d_in[8];
    const float* W1  = (const float*)d_in[9];
    const float* b1  = (const float*)d_in[10];
    const float* W2  = (const float*)d_in[11];
    const float* b2  = (const float*)d_in[12];
    const float* g1  = (const float*)d_in[13];
    const float* be1 = (const float*)d_in[14];
    const float* g2  = (const float*)d_in[15];
    const float* be2 = (const float*)d_in[16];
    float* out = (float*)d_out;

    float *tmp, *h;
    cudaGetSymbolAddress((void**)&tmp, g_tmp);
    cudaGetSymbolAddress((void**)&h, g_h);

    __nv_bfloat16 *xh, *xl, *qh, *ql, *kh, *kl, *vh, *vl;
    __nv_bfloat16 *ach, *acl, *hh, *hl, *ffh, *ffl;
    __nv_bfloat16 *Wqh, *Wql, *Wkh, *Wkl, *Wvh, *Wvl, *Woh, *Wol;
    __nv_bfloat16 *W1h, *W1l, *W2h, *W2l;
    cudaGetSymbolAddress((void**)&xh, g_xh);   cudaGetSymbolAddress((void**)&xl, g_xl);
    cudaGetSymbolAddress((void**)&qh, g_qh);   cudaGetSymbolAddress((void**)&ql, g_ql);
    cudaGetSymbolAddress((void**)&kh, g_kh);   cudaGetSymbolAddress((void**)&kl, g_kl);
    cudaGetSymbolAddress((void**)&vh, g_vh);   cudaGetSymbolAddress((void**)&vl, g_vl);
    cudaGetSymbolAddress((void**)&ach, g_ach); cudaGetSymbolAddress((void**)&acl, g_acl);
    cudaGetSymbolAddress((void**)&hh, g_hh);   cudaGetSymbolAddress((void**)&hl, g_hl);
    cudaGetSymbolAddress((void**)&ffh, g_ffh); cudaGetSymbolAddress((void**)&ffl, g_ffl);
    cudaGetSymbolAddress((void**)&Wqh, g_Wqh); cudaGetSymbolAddress((void**)&Wql, g_Wql);
    cudaGetSymbolAddress((void**)&Wkh, g_Wkh); cudaGetSymbolAddress((void**)&Wkl, g_Wkl);
    cudaGetSymbolAddress((void**)&Wvh, g_Wvh); cudaGetSymbolAddress((void**)&Wvl, g_Wvl);
    cudaGetSymbolAddress((void**)&Woh, g_Woh); cudaGetSymbolAddress((void**)&Wol, g_Wol);
    cudaGetSymbolAddress((void**)&W1h, g_W1h); cudaGetSymbolAddress((void**)&W1l, g_W1l);
    cudaGetSymbolAddress((void**)&W2h, g_W2h); cudaGetSymbolAddress((void**)&W2l, g_W2l);

    cudaFuncSetAttribute(flash_mma,
                         cudaFuncAttributeMaxDynamicSharedMemorySize, FL_SMEM);
    cudaFuncSetAttribute(gemm_mma,
                         cudaFuncAttributeMaxDynamicSharedMemorySize, GEMM_SMEM);

    const int CT = 256;
    #define CONV(src, dh, dl, n) \
        f32_split<<<((n) / 8 + CT - 1) / CT, CT>>>(src, dh, dl, (n) / 8)

    // standalone conversions: input x + the 6 weights
    CONV(x,  xh,  xl,  TOK * DM);
    CONV(Wq, Wqh, Wql, DM * DM);
    CONV(Wk, Wkh, Wkl, DM * DM);
    CONV(Wv, Wvh, Wvl, DM * DM);
    CONV(Wo, Woh, Wol, DM * DM);
    CONV(W1, W1h, W1l, DFF * DM);
    CONV(W2, W2h, W2l, DM * DFF);

    // QKV projections -> split-bf16 directly (Q pre-scaled by 1/sqrt(dh))
    gemm_mma<<<dim3(DM / BN, TOK / BM), 256, GEMM_SMEM>>>(xh, xl, Wqh, Wql, bq,
        nullptr, qh, ql, TOK, DM, DM, 0, 0.125f);
    gemm_mma<<<dim3(DM / BN, TOK / BM), 256, GEMM_SMEM>>>(xh, xl, Wkh, Wkl, bk,
        nullptr, kh, kl, TOK, DM, DM, 0, 1.0f);
    gemm_mma<<<dim3(DM / BN, TOK / BM), 256, GEMM_SMEM>>>(xh, xl, Wvh, Wvl, bv,
        nullptr, vh, vl, TOK, DM, DM, 0, 1.0f);

    // Attention (tensor cores, Q tile 128) -> split-bf16 concat-heads output
    flash_mma<<<dim3(SEQ / QT, 2 * NH), 256, FL_SMEM>>>(qh, ql, kh, kl, vh, vl,
                                                        ach, acl);

    // Output projection (fp32 out) + residual + LN1 (fp32 h + split for FFN)
    gemm_mma<<<dim3(DM / BN, TOK / BM), 256, GEMM_SMEM>>>(ach, acl, Woh, Wol, bo,
        tmp, nullptr, nullptr, TOK, DM, DM, 0, 1.0f);
    add_ln<<<TOK, 256>>>(x, tmp, g1, be1, h, hh, hl);

    // FFN: W1 (+ReLU) -> split-bf16 only; W2 -> fp32
    gemm_mma<<<dim3(DFF / BN, TOK / BM), 256, GEMM_SMEM>>>(hh, hl, W1h, W1l, b1,
        nullptr, ffh, ffl, TOK, DFF, DM, 1, 1.0f);
    gemm_mma<<<dim3(DM / BN, TOK / BM), 256, GEMM_SMEM>>>(ffh, ffl, W2h, W2l, b2,
        tmp, nullptr, nullptr, TOK, DM, DFF, 0, 1.0f);

    // Residual + LN2 -> output
    add_ln<<<TOK, 256>>>(h, tmp, g2, be2, out, nullptr, nullptr);

    #undef CONV
}